// round 1
// baseline (speedup 1.0000x reference)
#include <cuda_runtime.h>
#include <math_constants.h>

#define N_KEYS 65536
#define NQ     8192
#define D      66
#define TQ     32          // queries per block
#define CK     64          // keys per chunk
#define DX     80          // padded x width (40 f32x2 pairs = 8 groups * 5)
#define THREADS 256
#define NCHUNK (N_KEYS / CK)

// Scratch for K = x @ Wk^T + bk  (17.3 MB, static device allocation)
__device__ float g_K[(size_t)N_KEYS * D];

// ---- packed fp32x2 helpers (sm_103a) ----
__device__ __forceinline__ unsigned long long fma2(unsigned long long a,
                                                   unsigned long long b,
                                                   unsigned long long c) {
    unsigned long long d;
    asm("fma.rn.f32x2 %0, %1, %2, %3;" : "=l"(d) : "l"(a), "l"(b), "l"(c));
    return d;
}
__device__ __forceinline__ unsigned long long mul2(unsigned long long a,
                                                   unsigned long long b) {
    unsigned long long d;
    asm("mul.rn.f32x2 %0, %1, %2;" : "=l"(d) : "l"(a), "l"(b));
    return d;
}
union F2 { unsigned long long u; float2 f; };

// ============================================================
// Kernel 1: K[n][d] = sum_j x[n][j] * Wk[d][j] + bk[d]
// ============================================================
__global__ void __launch_bounds__(THREADS)
compute_k_kernel(const float* __restrict__ x,
                 const float* __restrict__ Wk,
                 const float* __restrict__ bk) {
    __shared__ float sx[64 * D];
    int tid = threadIdx.x;
    int rbase = blockIdx.x * 64;

    for (int i = tid; i < 64 * D; i += THREADS)
        sx[i] = x[(size_t)rbase * D + i];
    __syncthreads();

    for (int i = tid; i < 64 * D; i += THREADS) {
        int r = i / D, d = i % D;
        float acc = __ldg(bk + d);
        const float* w  = Wk + d * D;
        const float* xr = sx + r * D;
        #pragma unroll
        for (int j = 0; j < D; j++)
            acc += xr[j] * __ldg(w + j);
        g_K[(size_t)(rbase + r) * D + d] = acc;
    }
}

// ============================================================
// Kernel 2: fused flash-style attention selector (fp32)
//   per block: TQ=32 queries, stream CK=64 key chunks
// ============================================================
__global__ void __launch_bounds__(THREADS)
flash_kernel(const float* __restrict__ x,
             const float* __restrict__ query,
             float* __restrict__ out) {
    __shared__ __align__(16) float sQ[TQ * D];
    __shared__ __align__(16) float sK[CK * D];
    __shared__ __align__(16) float sX[CK * DX];
    __shared__ __align__(16) float sS[TQ * (CK + 1)];
    __shared__ float sM[TQ], sL[TQ], sA[TQ];

    const int tid   = threadIdx.x;
    const int qbase = blockIdx.x * TQ;

    // init
    for (int i = tid; i < TQ * D; i += THREADS)
        sQ[i] = query[(size_t)qbase * D + i];
    for (int i = tid; i < CK * DX; i += THREADS)
        sX[i] = 0.0f;                      // pad cols (66..79) stay zero forever
    if (tid < TQ) { sM[tid] = -CUDART_INF_F; sL[tid] = 0.0f; sA[tid] = 0.0f; }

    // phase-1 mapping: 16x16 thread grid, 2q x 4k register tile
    const int tx = tid & 15;
    const int ty = tid >> 4;
    // phase-2 mapping
    const int lane = tid & 31;
    const int warp = tid >> 5;
    // phase-3 mapping: 1 q-row x 5 d-pairs per thread
    const int b = tid & 7;      // d-pair group: pairs b + 8c, c<5
    const int g = tid >> 3;     // query row 0..31

    unsigned long long o[5];
    #pragma unroll
    for (int c = 0; c < 5; c++) o[c] = 0ull;

    for (int ch = 0; ch < NCHUNK; ch++) {
        __syncthreads();   // protect sK/sX/sS from previous iteration readers

        const size_t kb = (size_t)ch * CK;
        for (int i = tid; i < CK * D; i += THREADS)
            sK[i] = g_K[kb * D + i];
        for (int i = tid; i < CK * D; i += THREADS) {
            int r = i / D, c = i % D;
            sX[r * DX + c] = x[kb * D + i];
        }
        __syncthreads();

        // ---- phase 1: S[32][64] = Q . K^T  (f32x2 along k) ----
        {
            unsigned long long acc[2][4];
            #pragma unroll
            for (int i = 0; i < 2; i++)
                #pragma unroll
                for (int u = 0; u < 4; u++) acc[i][u] = 0ull;

            const unsigned long long* q0 =
                (const unsigned long long*)(sQ + (ty * 2) * D);
            const unsigned long long* q1 =
                (const unsigned long long*)(sQ + (ty * 2 + 1) * D);

            #pragma unroll
            for (int kp = 0; kp < D / 2; kp++) {
                unsigned long long qa = q0[kp];
                unsigned long long qb = q1[kp];
                #pragma unroll
                for (int u = 0; u < 4; u++) {
                    unsigned long long kv = *(const unsigned long long*)
                        (sK + (tx + 16 * u) * D + 2 * kp);
                    acc[0][u] = fma2(qa, kv, acc[0][u]);
                    acc[1][u] = fma2(qb, kv, acc[1][u]);
                }
            }
            #pragma unroll
            for (int i = 0; i < 2; i++)
                #pragma unroll
                for (int u = 0; u < 4; u++) {
                    F2 t; t.u = acc[i][u];
                    sS[(ty * 2 + i) * (CK + 1) + tx + 16 * u] = t.f.x + t.f.y;
                }
        }
        __syncthreads();

        // ---- phase 2: online softmax stats (warp w owns rows 4w..4w+3) ----
        #pragma unroll
        for (int i = 0; i < 4; i++) {
            int r = warp * 4 + i;
            float v0 = sS[r * (CK + 1) + lane];
            float v1 = sS[r * (CK + 1) + lane + 32];
            float mx = fmaxf(v0, v1);
            #pragma unroll
            for (int off = 16; off > 0; off >>= 1)
                mx = fmaxf(mx, __shfl_xor_sync(0xffffffffu, mx, off));
            float mOld = sM[r];
            float mNew = fmaxf(mOld, mx);
            float p0 = __expf(v0 - mNew);
            float p1 = __expf(v1 - mNew);
            sS[r * (CK + 1) + lane]      = p0;
            sS[r * (CK + 1) + lane + 32] = p1;
            float s = p0 + p1;
            #pragma unroll
            for (int off = 16; off > 0; off >>= 1)
                s += __shfl_xor_sync(0xffffffffu, s, off);
            if (lane == 0) {
                float alpha = __expf(mOld - mNew);
                sA[r] = alpha;
                sL[r] = sL[r] * alpha + s;
                sM[r] = mNew;
            }
        }
        __syncthreads();

        // ---- phase 3: O = O*alpha + P @ X  (f32x2 along d) ----
        {
            float alpha = sA[g];
            F2 a2; a2.f.x = alpha; a2.f.y = alpha;
            #pragma unroll
            for (int c = 0; c < 5; c++) o[c] = mul2(o[c], a2.u);

            const float* prow = sS + g * (CK + 1);
            #pragma unroll 4
            for (int k = 0; k < CK; k++) {
                float p = prow[k];
                F2 p2; p2.f.x = p; p2.f.y = p;
                const unsigned long long* xr =
                    (const unsigned long long*)(sX + k * DX);
                #pragma unroll
                for (int c = 0; c < 5; c++)
                    o[c] = fma2(xr[b + 8 * c], p2.u, o[c]);
            }
        }
    }

    __syncthreads();
    // ---- finalize: divide by l, write fp32 output ----
    {
        float inv = 1.0f / sL[g];
        #pragma unroll
        for (int c = 0; c < 5; c++) {
            int pr = b + 8 * c;           // d-pair index; cols 2pr, 2pr+1
            if (pr <= 32) {               // pr=33..39 are zero padding
                F2 t; t.u = o[c];
                float* dst = out + (size_t)(qbase + g) * D + 2 * pr;
                dst[0] = t.f.x * inv;
                dst[1] = t.f.y * inv;
            }
        }
    }
}

// ============================================================
extern "C" void kernel_launch(void* const* d_in, const int* in_sizes, int n_in,
                              void* d_out, int out_size) {
    const float* x     = (const float*)d_in[0];
    const float* query = (const float*)d_in[1];
    const float* Wk    = (const float*)d_in[2];
    const float* bk    = (const float*)d_in[3];
    float* out = (float*)d_out;

    compute_k_kernel<<<N_KEYS / 64, THREADS>>>(x, Wk, bk);
    flash_kernel<<<NQ / TQ, THREADS>>>(x, query, out);
}

// round 2
// speedup vs baseline: 1.9755x; 1.9755x over previous
#include <cuda_runtime.h>
#include <math_constants.h>

#define D       66
#define N_KEYS  65536
#define NQ      8192
#define TQ      128          // queries per block tile
#define CK      128          // keys per chunk
#define SPLITS  4
#define KSPLIT  (N_KEYS / SPLITS)   // 16384
#define NCHUNK  (KSPLIT / CK)       // 128
#define THREADS 256
#define QTILES  (NQ / TQ)           // 64

#define SXW     80           // padded x row (40 f32x2 pairs)
#define SSW     130          // padded S row
#define NPAIRS  33           // real d-pairs (66 = 2*33)

// Scratch (static device allocations — no cudaMalloc)
__device__ float  g_KT[(size_t)D * N_KEYS];          // K transposed [d][n], 17.3 MB
__device__ float  g_part[(size_t)SPLITS * NQ * D];   // unnormalized partial O, 8.7 MB
__device__ float2 g_ml[(size_t)SPLITS * NQ];         // (m, l) per split/query

// ---- packed fp32x2 helpers (sm_103a) ----
__device__ __forceinline__ unsigned long long fma2(unsigned long long a,
                                                   unsigned long long b,
                                                   unsigned long long c) {
    unsigned long long d;
    asm("fma.rn.f32x2 %0, %1, %2, %3;" : "=l"(d) : "l"(a), "l"(b), "l"(c));
    return d;
}
__device__ __forceinline__ unsigned long long mul2(unsigned long long a,
                                                   unsigned long long b) {
    unsigned long long d;
    asm("mul.rn.f32x2 %0, %1, %2;" : "=l"(d) : "l"(a), "l"(b));
    return d;
}
union F2 { unsigned long long u; float2 f; };
__device__ __forceinline__ unsigned long long dup2(float v) {
    F2 t; t.f.x = v; t.f.y = v; return t.u;
}

// ============================================================
// Kernel 1: g_KT[d][n] = sum_j x[n][j]*Wk[d][j] + bk[d]
// ============================================================
__global__ void __launch_bounds__(128)
compute_kt_kernel(const float* __restrict__ x,
                  const float* __restrict__ Wk,
                  const float* __restrict__ bk) {
    __shared__ float sx[128 * 67];   // padded rows: no bank conflicts
    __shared__ float sw[66 * 66];
    const int t = threadIdx.x;
    const size_t base = (size_t)blockIdx.x * 128;

    for (int i = t; i < 128 * D; i += 128)
        sx[(i / D) * 67 + (i % D)] = x[base * D + i];
    for (int i = t; i < D * D; i += 128)
        sw[i] = Wk[i];
    __syncthreads();

    const float* xr = sx + t * 67;
    for (int d = 0; d < D; d++) {
        float acc = __ldg(bk + d);
        const float* w = sw + d * D;
        #pragma unroll
        for (int j = 0; j < D; j++)
            acc = fmaf(xr[j], w[j], acc);
        g_KT[(size_t)d * N_KEYS + base + t] = acc;   // coalesced
    }
}

// ============================================================
// Kernel 2: split-K flash attention selector
//   block = (q-tile of 128) x (key split of 16384), 256 threads
// ============================================================
extern __shared__ float smem[];

__global__ void __launch_bounds__(THREADS, 1)
flash_kernel(const float* __restrict__ x,
             const float* __restrict__ query) {
    float* sQ  = smem;                 // 128 x 66
    float* sKT = sQ  + TQ * D;         // 66 x 128 (j-major)
    float* sX  = sKT + D * CK;         // 128 x 80 (padded)
    float* sS  = sX  + CK * SXW;       // 128 x 130 (padded)
    float* sM  = sS  + TQ * SSW;
    float* sL  = sM  + TQ;
    float* sA  = sL  + TQ;

    const int tid   = threadIdx.x;
    const int qtile = blockIdx.x & (QTILES - 1);
    const int split = blockIdx.x >> 6;          // QTILES = 64
    const size_t qbase = (size_t)qtile * TQ;
    const size_t k0    = (size_t)split * KSPLIT;

    // init
    for (int i = tid; i < TQ * D; i += THREADS)
        sQ[i] = query[qbase * D + i];
    for (int i = tid; i < CK * SXW; i += THREADS)
        sX[i] = 0.0f;                            // pad cols stay zero
    if (tid < TQ) { sM[tid] = -CUDART_INF_F; sL[tid] = 0.0f; }

    // phase-1 mapping: 16 q-groups x 16 k-groups, tile 8q x 4 k-pairs
    const int qg16 = tid >> 4;
    const int kg   = tid & 15;
    // phase-2 mapping
    const int lane = tid & 31;
    const int warp = tid >> 5;
    // phase-3 mapping: 32 q-groups x 8 pair-groups, tile 4q x 5 pairs
    const int qg = tid >> 3;
    const int pg = tid & 7;

    unsigned long long o[4][5];
    #pragma unroll
    for (int i = 0; i < 4; i++)
        #pragma unroll
        for (int c = 0; c < 5; c++) o[i][c] = 0ull;

    for (int ch = 0; ch < NCHUNK; ch++) {
        __syncthreads();    // previous chunk's readers of sKT/sX/sS done

        const size_t kb = k0 + (size_t)ch * CK;
        // fill sKT (coalesced from transposed K)
        for (int i = tid; i < D * CK; i += THREADS) {
            int j = i >> 7, k = i & (CK - 1);
            sKT[i] = g_KT[(size_t)j * N_KEYS + kb + k];
        }
        // fill sX (real cols only; pads remain 0)
        for (int i = tid; i < CK * D; i += THREADS) {
            int r = i / D, c = i - r * D;
            sX[r * SXW + c] = x[kb * D + i];
        }
        __syncthreads();

        // ---- phase 1: S = Q . K^T, contract j, f32x2 along k ----
        {
            unsigned long long acc[8][4];
            #pragma unroll
            for (int i = 0; i < 8; i++)
                #pragma unroll
                for (int u = 0; u < 4; u++) acc[i][u] = 0ull;

            const float* qp = sQ + (qg16 * 8) * D;
            const float* kp = sKT + 2 * kg;

            #pragma unroll 3
            for (int j = 0; j < D; j++) {
                unsigned long long kv[4];
                #pragma unroll
                for (int u = 0; u < 4; u++)
                    kv[u] = *(const unsigned long long*)(kp + j * CK + 32 * u);
                #pragma unroll
                for (int i = 0; i < 8; i++) {
                    unsigned long long q2 = dup2(qp[i * D + j]);
                    #pragma unroll
                    for (int u = 0; u < 4; u++)
                        acc[i][u] = fma2(q2, kv[u], acc[i][u]);
                }
            }
            #pragma unroll
            for (int i = 0; i < 8; i++)
                #pragma unroll
                for (int u = 0; u < 4; u++) {
                    F2 t; t.u = acc[i][u];
                    *(float2*)(sS + (qg16 * 8 + i) * SSW + 2 * (kg + 16 * u)) = t.f;
                }
        }
        __syncthreads();

        // ---- phase 2: online softmax stats (warp w owns rows 16w..16w+15) ----
        #pragma unroll 4
        for (int rr = 0; rr < 16; rr++) {
            int r = warp * 16 + rr;
            float* row = sS + r * SSW;
            float v0 = row[lane];
            float v1 = row[lane + 32];
            float v2 = row[lane + 64];
            float v3 = row[lane + 96];
            float mx = fmaxf(fmaxf(v0, v1), fmaxf(v2, v3));
            #pragma unroll
            for (int off = 16; off > 0; off >>= 1)
                mx = fmaxf(mx, __shfl_xor_sync(0xffffffffu, mx, off));
            float mOld = sM[r];
            float mNew = fmaxf(mOld, mx);
            float p0 = __expf(v0 - mNew);
            float p1 = __expf(v1 - mNew);
            float p2 = __expf(v2 - mNew);
            float p3 = __expf(v3 - mNew);
            row[lane]      = p0;
            row[lane + 32] = p1;
            row[lane + 64] = p2;
            row[lane + 96] = p3;
            float s = (p0 + p1) + (p2 + p3);
            #pragma unroll
            for (int off = 16; off > 0; off >>= 1)
                s += __shfl_xor_sync(0xffffffffu, s, off);
            if (lane == 0) {
                float alpha = __expf(mOld - mNew);
                sA[r] = alpha;
                sL[r] = sL[r] * alpha + s;
                sM[r] = mNew;
            }
        }
        __syncthreads();

        // ---- phase 3: O = O*alpha + P @ X ----
        {
            #pragma unroll
            for (int i = 0; i < 4; i++) {
                unsigned long long a2 = dup2(sA[qg * 4 + i]);
                #pragma unroll
                for (int c = 0; c < 5; c++)
                    o[i][c] = mul2(o[i][c], a2);
            }
            const float* xp = sX + 2 * pg;
            const float* pp = sS + (qg * 4) * SSW;
            #pragma unroll 4
            for (int k = 0; k < CK; k++) {
                unsigned long long xv[5];
                #pragma unroll
                for (int c = 0; c < 5; c++)
                    xv[c] = *(const unsigned long long*)(xp + k * SXW + 16 * c);
                #pragma unroll
                for (int i = 0; i < 4; i++) {
                    unsigned long long p2 = dup2(pp[i * SSW + k]);
                    #pragma unroll
                    for (int c = 0; c < 5; c++)
                        o[i][c] = fma2(p2, xv[c], o[i][c]);
                }
            }
        }
    }

    __syncthreads();
    // ---- write partials ----
    if (tid < TQ)
        g_ml[(size_t)split * NQ + qbase + tid] = make_float2(sM[tid], sL[tid]);

    #pragma unroll
    for (int i = 0; i < 4; i++) {
        size_t q = qbase + qg * 4 + i;
        float* dst = g_part + ((size_t)split * NQ + q) * D;
        #pragma unroll
        for (int c = 0; c < 5; c++) {
            int pr = pg + 8 * c;
            if (pr < NPAIRS) {
                F2 t; t.u = o[i][c];
                *(float2*)(dst + 2 * pr) = t.f;
            }
        }
    }
}

// ============================================================
// Kernel 3: combine split-K partials
// ============================================================
__global__ void __launch_bounds__(256)
combine_kernel(float* __restrict__ out) {
    const int q = blockIdx.x * 256 + threadIdx.x;   // 8192 total
    float2 ml[SPLITS];
    float m = -CUDART_INF_F;
    #pragma unroll
    for (int s = 0; s < SPLITS; s++) {
        ml[s] = g_ml[(size_t)s * NQ + q];
        m = fmaxf(m, ml[s].x);
    }
    float w[SPLITS];
    float l = 0.0f;
    #pragma unroll
    for (int s = 0; s < SPLITS; s++) {
        w[s] = __expf(ml[s].x - m);
        l += w[s] * ml[s].y;
    }
    float inv = 1.0f / l;
    #pragma unroll 3
    for (int d = 0; d < D; d += 2) {
        float ax = 0.0f, ay = 0.0f;
        #pragma unroll
        for (int s = 0; s < SPLITS; s++) {
            float2 v = *(const float2*)(g_part + ((size_t)s * NQ + q) * D + d);
            ax = fmaf(w[s], v.x, ax);
            ay = fmaf(w[s], v.y, ay);
        }
        out[(size_t)q * D + d]     = ax * inv;
        out[(size_t)q * D + d + 1] = ay * inv;
    }
}

// ============================================================
extern "C" void kernel_launch(void* const* d_in, const int* in_sizes, int n_in,
                              void* d_out, int out_size) {
    const float* x     = (const float*)d_in[0];
    const float* query = (const float*)d_in[1];
    const float* Wk    = (const float*)d_in[2];
    const float* bk    = (const float*)d_in[3];
    float* out = (float*)d_out;

    const int smem_bytes = (TQ * D + D * CK + CK * SXW + TQ * SSW + 3 * TQ) * 4;
    cudaFuncSetAttribute(flash_kernel,
                         cudaFuncAttributeMaxDynamicSharedMemorySize, smem_bytes);

    compute_kt_kernel<<<N_KEYS / 128, 128>>>(x, Wk, bk);
    flash_kernel<<<QTILES * SPLITS, THREADS, smem_bytes>>>(x, query);
    combine_kernel<<<NQ / 256, 256>>>(out);
}

// round 3
// speedup vs baseline: 7.3753x; 3.7335x over previous
#include <cuda_runtime.h>
#include <cuda_bf16.h>
#include <cstdint>

#define D66     66
#define DP      80
#define NK      65536
#define NQT     8192
#define SPLITS  4
#define KSPLIT  (NK / SPLITS)      // 16384
#define CK      64
#define NCHUNK  (KSPLIT / CK)      // 256
#define SKW     88                 // smem row pitch (bf16 elems) -> conflict-free ldmatrix
#define ABYTES  (CK * SKW * 2)     // 11264 per array
#define BUFBYTES (4 * ABYTES)      // 45056 per buffer
#define MSTATIC 32.0f

// static device scratch (no cudaMalloc)
__device__ __nv_bfloat16 g_prep[(size_t)4 * NK * DP];       // [Kh][Kl][Xh][Xl], 42 MB
__device__ float g_part[(size_t)SPLITS * NQT * D66];        // unnormalized O partials
__device__ float g_l[SPLITS * NQT];                          // softmax denominators

// ---------------- asm helpers ----------------
#define MMA_BF16(dv, av, b0_, b1_)                                          \
    asm volatile("mma.sync.aligned.m16n8k16.row.col.f32.bf16.bf16.f32 "     \
                 "{%0,%1,%2,%3},{%4,%5,%6,%7},{%8,%9},{%0,%1,%2,%3};"       \
                 : "+f"(dv[0]), "+f"(dv[1]), "+f"(dv[2]), "+f"(dv[3])       \
                 : "r"(av[0]), "r"(av[1]), "r"(av[2]), "r"(av[3]),          \
                   "r"(b0_), "r"(b1_))

#define LDSM4(r0, r1, r2, r3, ad)                                           \
    asm volatile("ldmatrix.sync.aligned.m8n8.x4.shared.b16 {%0,%1,%2,%3},[%4];" \
                 : "=r"(r0), "=r"(r1), "=r"(r2), "=r"(r3) : "r"(ad))

#define LDSM4T(r0, r1, r2, r3, ad)                                          \
    asm volatile("ldmatrix.sync.aligned.m8n8.x4.trans.shared.b16 {%0,%1,%2,%3},[%4];" \
                 : "=r"(r0), "=r"(r1), "=r"(r2), "=r"(r3) : "r"(ad))

#define LDSM2T(r0, r1, ad)                                                  \
    asm volatile("ldmatrix.sync.aligned.m8n8.x2.trans.shared.b16 {%0,%1},[%2];" \
                 : "=r"(r0), "=r"(r1) : "r"(ad))

__device__ __forceinline__ void cp16(uint32_t dst, const void* src) {
    asm volatile("cp.async.cg.shared.global [%0],[%1],16;" :: "r"(dst), "l"(src));
}
__device__ __forceinline__ void cpcommit() { asm volatile("cp.async.commit_group;"); }
__device__ __forceinline__ void cpwait1()  { asm volatile("cp.async.wait_group 1;"); }
__device__ __forceinline__ void cpwait0()  { asm volatile("cp.async.wait_group 0;"); }

// split two floats into packed bf16 hi / bf16 lo pairs
__device__ __forceinline__ void split2(float x, float y, uint32_t& hi, uint32_t& lo) {
    __nv_bfloat162 h = __floats2bfloat162_rn(x, y);
    hi = *reinterpret_cast<uint32_t*>(&h);
    float rx = x - __bfloat162float(h.x);
    float ry = y - __bfloat162float(h.y);
    __nv_bfloat162 l = __floats2bfloat162_rn(rx, ry);
    lo = *reinterpret_cast<uint32_t*>(&l);
}

// ============================================================
// Kernel 1: prep — K = x@Wk^T + bk; write Kh/Kl/Xh/Xl bf16, padded to DP=80
// ============================================================
__global__ void __launch_bounds__(128)
prep_kernel(const float* __restrict__ x,
            const float* __restrict__ Wk,
            const float* __restrict__ bk) {
    __shared__ float sw[D66 * D66];
    __shared__ float sb[D66];
    const int tid = threadIdx.x;
    const int n = blockIdx.x * 128 + tid;

    for (int i = tid; i < D66 * D66; i += 128) sw[i] = Wk[i];
    if (tid < D66) sb[tid] = bk[tid];
    __syncthreads();

    float xr[D66];
    const float2* xp = (const float2*)(x + (size_t)n * D66);
    #pragma unroll
    for (int c = 0; c < 33; c++) {
        float2 v = xp[c];
        xr[2 * c] = v.x; xr[2 * c + 1] = v.y;
    }

    const size_t NA = (size_t)NK * DP;
    __nv_bfloat16* Kh = g_prep;
    __nv_bfloat16* Kl = g_prep + NA;
    __nv_bfloat16* Xh = g_prep + 2 * NA;
    __nv_bfloat16* Xl = g_prep + 3 * NA;
    const size_t rb = (size_t)n * DP;

    // X split
    #pragma unroll
    for (int c = 0; c < 33; c++) {
        uint32_t hi, lo;
        split2(xr[2 * c], xr[2 * c + 1], hi, lo);
        *(uint32_t*)(Xh + rb + 2 * c) = hi;
        *(uint32_t*)(Xl + rb + 2 * c) = lo;
    }
    // K rows + split
    #pragma unroll 2
    for (int dd = 0; dd < 33; dd++) {
        int d0 = 2 * dd;
        float a0 = sb[d0], a1 = sb[d0 + 1];
        const float* w0 = sw + d0 * D66;
        const float* w1 = w0 + D66;
        #pragma unroll
        for (int j = 0; j < D66; j++) {
            a0 = fmaf(xr[j], w0[j], a0);
            a1 = fmaf(xr[j], w1[j], a1);
        }
        uint32_t hi, lo;
        split2(a0, a1, hi, lo);
        *(uint32_t*)(Kh + rb + d0) = hi;
        *(uint32_t*)(Kl + rb + d0) = lo;
    }
    // pads (cols 66..79)
    #pragma unroll
    for (int c = 33; c < 40; c++) {
        *(uint32_t*)(Kh + rb + 2 * c) = 0u;
        *(uint32_t*)(Kl + rb + 2 * c) = 0u;
        *(uint32_t*)(Xh + rb + 2 * c) = 0u;
        *(uint32_t*)(Xl + rb + 2 * c) = 0u;
    }
}

// ============================================================
// Kernel 2: flash attention selector (HMMA bf16x3, static max)
// ============================================================
extern __shared__ __nv_bfloat16 smbuf[];

__global__ void __launch_bounds__(256, 1)
flash_kernel(const float* __restrict__ query) {
    const int tid  = threadIdx.x;
    const int lane = tid & 31;
    const int w    = tid >> 5;                 // 8 warps
    const int qtile = blockIdx.x & 63;
    const int split = blockIdx.x >> 6;
    const int q0 = qtile * 128 + w * 16;       // this warp's 16 q rows
    const size_t k0 = (size_t)split * KSPLIT;

    const int g  = lane >> 2;
    const int t  = lane & 3;
    const int q8 = lane >> 3;
    const int r  = lane & 7;

    const uint32_t sbase = (uint32_t)__cvta_generic_to_shared(smbuf);

    // ---- Q fragments (one-time, straight from gmem fp32) ----
    uint32_t aqh[5][4], aql[5][4];
    {
        const int qr0 = q0 + g;
        const int qr1 = q0 + g + 8;
        #pragma unroll
        for (int kc = 0; kc < 5; kc++) {
            int c0 = 16 * kc + 2 * t;
            int c2 = c0 + 8;
            float2 v00 = (c0 < D66) ? *(const float2*)(query + (size_t)qr0 * D66 + c0) : make_float2(0.f, 0.f);
            float2 v10 = (c0 < D66) ? *(const float2*)(query + (size_t)qr1 * D66 + c0) : make_float2(0.f, 0.f);
            float2 v01 = (c2 < D66) ? *(const float2*)(query + (size_t)qr0 * D66 + c2) : make_float2(0.f, 0.f);
            float2 v11 = (c2 < D66) ? *(const float2*)(query + (size_t)qr1 * D66 + c2) : make_float2(0.f, 0.f);
            split2(v00.x, v00.y, aqh[kc][0], aql[kc][0]);
            split2(v10.x, v10.y, aqh[kc][1], aql[kc][1]);
            split2(v01.x, v01.y, aqh[kc][2], aql[kc][2]);
            split2(v11.x, v11.y, aqh[kc][3], aql[kc][3]);
        }
    }

    // ---- lane-constant ldmatrix offsets (bytes) ----
    const uint32_t qk_off  = ((8 * (q8 >> 1) + r) * SKW + 8 * (q8 & 1)) * 2;
    const uint32_t pv_off  = ((8 * (q8 & 1) + r) * SKW + 8 * (q8 >> 1)) * 2;
    const uint32_t pv2_off = ((8 * (q8 & 1) + r) * SKW + 64) * 2;

    float o[9][4];
    #pragma unroll
    for (int i = 0; i < 9; i++)
        #pragma unroll
        for (int c = 0; c < 4; c++) o[i][c] = 0.0f;
    float lsum0 = 0.0f, lsum1 = 0.0f;

    // ---- prefetch lambda-ish (macro via loop) ----
    #define PREFETCH(CH)                                                         \
    do {                                                                          \
        const size_t kb = k0 + (size_t)(CH) * CK;                                 \
        const uint32_t bb = sbase + ((CH) & 1) * BUFBYTES;                        \
        _Pragma("unroll")                                                         \
        for (int jj = 0; jj < 10; jj++) {                                         \
            int j = tid + jj * 256;                                               \
            int arr = j / 640;                                                    \
            int rem = j - arr * 640;                                              \
            int row = rem / 10;                                                   \
            int cc  = rem - row * 10;                                             \
            const __nv_bfloat16* src = g_prep + (size_t)arr * ((size_t)NK * DP)   \
                                       + (kb + row) * DP + cc * 8;                \
            uint32_t dst = bb + arr * ABYTES + (row * SKW + cc * 8) * 2;          \
            cp16(dst, src);                                                       \
        }                                                                         \
    } while (0)

    PREFETCH(0); cpcommit();

    for (int ch = 0; ch < NCHUNK; ch++) {
        if (ch + 1 < NCHUNK) { PREFETCH(ch + 1); cpcommit(); cpwait1(); }
        else                 { cpwait0(); }
        __syncthreads();

        const uint32_t bb  = sbase + (ch & 1) * BUFBYTES;
        const uint32_t sKh = bb;
        const uint32_t sKl = bb + ABYTES;
        const uint32_t sXh = bb + 2 * ABYTES;
        const uint32_t sXl = bb + 3 * ABYTES;

        // ---- QK: S[16 x 64] = Qh·Kh + Qh·Kl + Ql·Kh ----
        float s[8][4];
        #pragma unroll
        for (int i = 0; i < 8; i++)
            #pragma unroll
            for (int c = 0; c < 4; c++) s[i][c] = 0.0f;

        #pragma unroll
        for (int kc = 0; kc < 5; kc++) {
            #pragma unroll
            for (int jn2 = 0; jn2 < 4; jn2++) {
                uint32_t off = (16 * jn2 * SKW + 16 * kc) * 2 + qk_off;
                uint32_t bh0, bh1, bh2, bh3, bl0, bl1, bl2, bl3;
                LDSM4(bh0, bh1, bh2, bh3, sKh + off);
                LDSM4(bl0, bl1, bl2, bl3, sKl + off);
                MMA_BF16(s[2 * jn2],     aqh[kc], bh0, bh1);
                MMA_BF16(s[2 * jn2],     aqh[kc], bl0, bl1);
                MMA_BF16(s[2 * jn2],     aql[kc], bh0, bh1);
                MMA_BF16(s[2 * jn2 + 1], aqh[kc], bh2, bh3);
                MMA_BF16(s[2 * jn2 + 1], aqh[kc], bl2, bl3);
                MMA_BF16(s[2 * jn2 + 1], aql[kc], bh2, bh3);
            }
        }

        // ---- softmax (static max) + P fragment packing ----
        uint32_t pah[4][4], pal[4][4];
        #pragma unroll
        for (int u = 0; u < 4; u++) {
            float e00 = __expf(s[2 * u][0] - MSTATIC);
            float e01 = __expf(s[2 * u][1] - MSTATIC);
            float e02 = __expf(s[2 * u][2] - MSTATIC);
            float e03 = __expf(s[2 * u][3] - MSTATIC);
            float e10 = __expf(s[2 * u + 1][0] - MSTATIC);
            float e11 = __expf(s[2 * u + 1][1] - MSTATIC);
            float e12 = __expf(s[2 * u + 1][2] - MSTATIC);
            float e13 = __expf(s[2 * u + 1][3] - MSTATIC);
            lsum0 += (e00 + e01) + (e10 + e11);
            lsum1 += (e02 + e03) + (e12 + e13);
            split2(e00, e01, pah[u][0], pal[u][0]);
            split2(e02, e03, pah[u][1], pal[u][1]);
            split2(e10, e11, pah[u][2], pal[u][2]);
            split2(e12, e13, pah[u][3], pal[u][3]);
        }

        // ---- PV: O[16 x 72] += Ph·Xh + Ph·Xl + Pl·Xh ----
        #pragma unroll
        for (int kc2 = 0; kc2 < 4; kc2++) {
            #pragma unroll
            for (int dn2 = 0; dn2 < 4; dn2++) {
                uint32_t off = (16 * kc2 * SKW + 16 * dn2) * 2 + pv_off;
                uint32_t bh0, bh1, bh2, bh3, bl0, bl1, bl2, bl3;
                LDSM4T(bh0, bh1, bh2, bh3, sXh + off);
                LDSM4T(bl0, bl1, bl2, bl3, sXl + off);
                MMA_BF16(o[2 * dn2],     pah[kc2], bh0, bh1);
                MMA_BF16(o[2 * dn2],     pah[kc2], bl0, bl1);
                MMA_BF16(o[2 * dn2],     pal[kc2], bh0, bh1);
                MMA_BF16(o[2 * dn2 + 1], pah[kc2], bh2, bh3);
                MMA_BF16(o[2 * dn2 + 1], pah[kc2], bl2, bl3);
                MMA_BF16(o[2 * dn2 + 1], pal[kc2], bh2, bh3);
            }
            { // dn = 8 (cols 64..71)
                uint32_t off = (16 * kc2 * SKW) * 2 + pv2_off;
                uint32_t bh0, bh1, bl0, bl1;
                LDSM2T(bh0, bh1, sXh + off);
                LDSM2T(bl0, bl1, sXl + off);
                MMA_BF16(o[8], pah[kc2], bh0, bh1);
                MMA_BF16(o[8], pah[kc2], bl0, bl1);
                MMA_BF16(o[8], pal[kc2], bh0, bh1);
            }
        }
        __syncthreads();
    }

    // ---- epilogue: reduce l within quads, write partials ----
    lsum0 += __shfl_xor_sync(0xffffffffu, lsum0, 1);
    lsum0 += __shfl_xor_sync(0xffffffffu, lsum0, 2);
    lsum1 += __shfl_xor_sync(0xffffffffu, lsum1, 1);
    lsum1 += __shfl_xor_sync(0xffffffffu, lsum1, 2);
    if ((lane & 3) == 0) {
        g_l[split * NQT + q0 + g]     = lsum0;
        g_l[split * NQT + q0 + g + 8] = lsum1;
    }
    const size_t ob = (size_t)split * NQT;
    #pragma unroll
    for (int dn = 0; dn < 9; dn++) {
        int d0 = 8 * dn + 2 * t;
        if (d0 < D66) {
            *(float2*)(g_part + (ob + q0 + g)     * D66 + d0) = make_float2(o[dn][0], o[dn][1]);
            *(float2*)(g_part + (ob + q0 + g + 8) * D66 + d0) = make_float2(o[dn][2], o[dn][3]);
        }
    }
}

// ============================================================
// Kernel 3: combine splits (plain sums — static max)
// ============================================================
__global__ void __launch_bounds__(256)
combine_kernel(float* __restrict__ out) {
    const int q = blockIdx.x * 256 + threadIdx.x;
    float l = 0.0f;
    #pragma unroll
    for (int s = 0; s < SPLITS; s++) l += g_l[s * NQT + q];
    float inv = 1.0f / l;
    #pragma unroll 3
    for (int c = 0; c < 33; c++) {
        float ax = 0.0f, ay = 0.0f;
        #pragma unroll
        for (int s = 0; s < SPLITS; s++) {
            float2 v = *(const float2*)(g_part + ((size_t)s * NQT + q) * D66 + 2 * c);
            ax += v.x; ay += v.y;
        }
        out[(size_t)q * D66 + 2 * c]     = ax * inv;
        out[(size_t)q * D66 + 2 * c + 1] = ay * inv;
    }
}

// ============================================================
extern "C" void kernel_launch(void* const* d_in, const int* in_sizes, int n_in,
                              void* d_out, int out_size) {
    const float* x     = (const float*)d_in[0];
    const float* query = (const float*)d_in[1];
    const float* Wk    = (const float*)d_in[2];
    const float* bk    = (const float*)d_in[3];
    float* out = (float*)d_out;

    const int smem_bytes = 2 * BUFBYTES;   // 90112
    cudaFuncSetAttribute(flash_kernel,
                         cudaFuncAttributeMaxDynamicSharedMemorySize, smem_bytes);

    prep_kernel<<<NK / 128, 128>>>(x, Wk, bk);
    flash_kernel<<<64 * SPLITS, 256, smem_bytes>>>(query);
    combine_kernel<<<NQT / 256, 256>>>(out);
}

// round 5
// speedup vs baseline: 10.3593x; 1.4046x over previous
#include <cuda_runtime.h>
#include <cuda_fp16.h>
#include <math_constants.h>
#include <cstdint>

#define D66     66
#define DP      80
#define NK      65536
#define NQT     8192
#define SPLITS  16
#define KSPLIT  (NK / SPLITS)      // 4096
#define CK      64
#define NCH     (KSPLIT / CK)      // 64 chunks per block
#define SKW     88                 // smem row pitch (fp16 elems), conflict-free ldmatrix
#define ABYTES  (CK * SKW * 2)     // 11264
#define NARR    3                  // Kh, Kl, Xh
#define CHUNK_B (NARR * ABYTES)    // 33792
#define GROUPS  (NARR * CK * 10)   // 1920 16B-groups per chunk

// static device scratch (no cudaMalloc)
__device__ __align__(16) __half g_prep[(size_t)NARR * NK * DP];   // 31.5 MB
__device__ float  g_part[(size_t)SPLITS * NQT * D66];             // 34.6 MB
__device__ float2 g_ml[SPLITS * NQT];

// ---------------- asm helpers ----------------
#define MMA_F16(dv, av, b0_, b1_)                                           \
    asm volatile("mma.sync.aligned.m16n8k16.row.col.f32.f16.f16.f32 "       \
                 "{%0,%1,%2,%3},{%4,%5,%6,%7},{%8,%9},{%0,%1,%2,%3};"       \
                 : "+f"(dv[0]), "+f"(dv[1]), "+f"(dv[2]), "+f"(dv[3])       \
                 : "r"(av[0]), "r"(av[1]), "r"(av[2]), "r"(av[3]),          \
                   "r"(b0_), "r"(b1_))

#define LDSM4(r0, r1, r2, r3, ad)                                           \
    asm volatile("ldmatrix.sync.aligned.m8n8.x4.shared.b16 {%0,%1,%2,%3},[%4];" \
                 : "=r"(r0), "=r"(r1), "=r"(r2), "=r"(r3) : "r"(ad))

#define LDSM4T(r0, r1, r2, r3, ad)                                          \
    asm volatile("ldmatrix.sync.aligned.m8n8.x4.trans.shared.b16 {%0,%1,%2,%3},[%4];" \
                 : "=r"(r0), "=r"(r1), "=r"(r2), "=r"(r3) : "r"(ad))

#define LDSM2T(r0, r1, ad)                                                  \
    asm volatile("ldmatrix.sync.aligned.m8n8.x2.trans.shared.b16 {%0,%1},[%2];" \
                 : "=r"(r0), "=r"(r1) : "r"(ad))

__device__ __forceinline__ void cp16(uint32_t dst, const void* src) {
    asm volatile("cp.async.cg.shared.global [%0],[%1],16;" :: "r"(dst), "l"(src));
}
__device__ __forceinline__ void cpcommit() { asm volatile("cp.async.commit_group;"); }
__device__ __forceinline__ void cpwait1()  { asm volatile("cp.async.wait_group 1;"); }
__device__ __forceinline__ void cpwait0()  { asm volatile("cp.async.wait_group 0;"); }

// split two floats into packed fp16 hi / fp16 lo (residual) pairs
__device__ __forceinline__ void split2h(float x, float y, uint32_t& hi, uint32_t& lo) {
    __half2 h = __floats2half2_rn(x, y);
    hi = *reinterpret_cast<uint32_t*>(&h);
    float rx = x - __low2float(h);
    float ry = y - __high2float(h);
    __half2 l = __floats2half2_rn(rx, ry);
    lo = *reinterpret_cast<uint32_t*>(&l);
}
__device__ __forceinline__ uint32_t pack2h(float x, float y) {
    __half2 h = __floats2half2_rn(x, y);
    return *reinterpret_cast<uint32_t*>(&h);
}

// ============================================================
// Kernel 1: prep — K = x@Wk^T + bk; write Kh/Kl (fp16 split) and Xh (fp16)
// row-major [n][80], cols 66..79 zero.
// ============================================================
__global__ void __launch_bounds__(128)
prep_kernel(const float* __restrict__ x,
            const float* __restrict__ Wk,
            const float* __restrict__ bk) {
    __shared__ float sw[D66 * D66];
    __shared__ float sb[D66];
    const int tid = threadIdx.x;
    const int n = blockIdx.x * 128 + tid;

    for (int i = tid; i < D66 * D66; i += 128) sw[i] = Wk[i];
    if (tid < D66) sb[tid] = bk[tid];
    __syncthreads();

    float xr[D66];
    const float2* xp = (const float2*)(x + (size_t)n * D66);
    #pragma unroll
    for (int c = 0; c < 33; c++) {
        float2 v = xp[c];
        xr[2 * c] = v.x; xr[2 * c + 1] = v.y;
    }

    const size_t NA = (size_t)NK * DP;
    __half* Kh = g_prep;
    __half* Kl = g_prep + NA;
    __half* Xh = g_prep + 2 * NA;
    const size_t rb = (size_t)n * DP;

    #pragma unroll
    for (int c = 0; c < 33; c++)
        *(uint32_t*)(Xh + rb + 2 * c) = pack2h(xr[2 * c], xr[2 * c + 1]);

    #pragma unroll 2
    for (int dd = 0; dd < 33; dd++) {
        int d0 = 2 * dd;
        float a0 = sb[d0], a1 = sb[d0 + 1];
        const float* w0 = sw + d0 * D66;
        const float* w1 = w0 + D66;
        #pragma unroll
        for (int j = 0; j < D66; j++) {
            a0 = fmaf(xr[j], w0[j], a0);
            a1 = fmaf(xr[j], w1[j], a1);
        }
        uint32_t hi, lo;
        split2h(a0, a1, hi, lo);
        *(uint32_t*)(Kh + rb + d0) = hi;
        *(uint32_t*)(Kl + rb + d0) = lo;
    }
    #pragma unroll
    for (int c = 33; c < 40; c++) {
        *(uint32_t*)(Kh + rb + 2 * c) = 0u;
        *(uint32_t*)(Kl + rb + 2 * c) = 0u;
        *(uint32_t*)(Xh + rb + 2 * c) = 0u;
    }
}

// ============================================================
// Kernel 2: flash attention selector
//   HMMA fp16: QK 3-pass (hi/lo exact), PV 1-pass, online row max.
// ============================================================
extern __shared__ __half smbuf[];

__global__ void __launch_bounds__(256, 1)
flash_kernel(const float* __restrict__ query) {
    const int tid  = threadIdx.x;
    const int lane = tid & 31;
    const int w    = tid >> 5;                 // 8 warps
    const int qtile = blockIdx.x & 63;
    const int split = blockIdx.x >> 6;         // 0..15
    const int q0 = qtile * 128 + w * 16;
    const size_t k0 = (size_t)split * KSPLIT;

    const int g  = lane >> 2;
    const int t  = lane & 3;
    const int q8 = lane >> 3;
    const int r  = lane & 7;

    const uint32_t sbase = (uint32_t)__cvta_generic_to_shared(smbuf);

    // ---- Q fragments (one-time, fp16 hi/lo) ----
    uint32_t aqh[5][4], aql[5][4];
    {
        const int qr0 = q0 + g;
        const int qr1 = q0 + g + 8;
        #pragma unroll
        for (int kc = 0; kc < 5; kc++) {
            int c0 = 16 * kc + 2 * t;
            int c2 = c0 + 8;
            float2 v00 = (c0 < D66) ? *(const float2*)(query + (size_t)qr0 * D66 + c0) : make_float2(0.f, 0.f);
            float2 v10 = (c0 < D66) ? *(const float2*)(query + (size_t)qr1 * D66 + c0) : make_float2(0.f, 0.f);
            float2 v01 = (c2 < D66) ? *(const float2*)(query + (size_t)qr0 * D66 + c2) : make_float2(0.f, 0.f);
            float2 v11 = (c2 < D66) ? *(const float2*)(query + (size_t)qr1 * D66 + c2) : make_float2(0.f, 0.f);
            split2h(v00.x, v00.y, aqh[kc][0], aql[kc][0]);
            split2h(v10.x, v10.y, aqh[kc][1], aql[kc][1]);
            split2h(v01.x, v01.y, aqh[kc][2], aql[kc][2]);
            split2h(v11.x, v11.y, aqh[kc][3], aql[kc][3]);
        }
    }

    const uint32_t qk_off  = ((8 * (q8 >> 1) + r) * SKW + 8 * (q8 & 1)) * 2;
    const uint32_t pv_off  = ((8 * (q8 & 1) + r) * SKW + 8 * (q8 >> 1)) * 2;
    const uint32_t pv2_off = ((8 * (q8 & 1) + r) * SKW + 64) * 2;

    float o[9][4];
    #pragma unroll
    for (int i = 0; i < 9; i++)
        #pragma unroll
        for (int c = 0; c < 4; c++) o[i][c] = 0.0f;
    float m0 = -CUDART_INF_F, m1 = -CUDART_INF_F;
    float l0 = 0.0f, l1 = 0.0f;

    #define PREFETCH(CH)                                                          \
    do {                                                                          \
        const size_t kb = k0 + (size_t)(CH) * CK;                                 \
        const uint32_t bb = sbase + ((CH) & 1) * CHUNK_B;                         \
        _Pragma("unroll")                                                         \
        for (int jj = 0; jj < 8; jj++) {                                          \
            int j = tid + jj * 256;                                               \
            if (j < GROUPS) {                                                     \
                int arr = j / 640;                                                \
                int rem = j - arr * 640;                                          \
                int row = rem / 10;                                               \
                int cc  = rem - row * 10;                                         \
                const __half* src = g_prep + (size_t)arr * ((size_t)NK * DP)      \
                                    + (kb + row) * DP + cc * 8;                   \
                uint32_t dst = bb + arr * ABYTES + (row * SKW + cc * 8) * 2;      \
                cp16(dst, src);                                                   \
            }                                                                     \
        }                                                                         \
    } while (0)

    PREFETCH(0); cpcommit();

    for (int ch = 0; ch < NCH; ch++) {
        if (ch + 1 < NCH) { PREFETCH(ch + 1); cpcommit(); cpwait1(); }
        else              { cpwait0(); }
        __syncthreads();

        const uint32_t bb  = sbase + (ch & 1) * CHUNK_B;
        const uint32_t sKh = bb;
        const uint32_t sKl = bb + ABYTES;
        const uint32_t sXh = bb + 2 * ABYTES;

        // ---- QK: S = Qh·Kh + Qh·Kl + Ql·Kh ----
        float s[8][4];
        #pragma unroll
        for (int i = 0; i < 8; i++)
            #pragma unroll
            for (int c = 0; c < 4; c++) s[i][c] = 0.0f;

        #pragma unroll
        for (int kc = 0; kc < 5; kc++) {
            #pragma unroll
            for (int jn2 = 0; jn2 < 4; jn2++) {
                uint32_t off = (16 * jn2 * SKW + 16 * kc) * 2 + qk_off;
                uint32_t bh0, bh1, bh2, bh3, bl0, bl1, bl2, bl3;
                LDSM4(bh0, bh1, bh2, bh3, sKh + off);
                LDSM4(bl0, bl1, bl2, bl3, sKl + off);
                MMA_F16(s[2 * jn2],     aqh[kc], bh0, bh1);
                MMA_F16(s[2 * jn2],     aqh[kc], bl0, bl1);
                MMA_F16(s[2 * jn2],     aql[kc], bh0, bh1);
                MMA_F16(s[2 * jn2 + 1], aqh[kc], bh2, bh3);
                MMA_F16(s[2 * jn2 + 1], aqh[kc], bl2, bl3);
                MMA_F16(s[2 * jn2 + 1], aql[kc], bh2, bh3);
            }
        }

        // ---- online softmax: row max, rescale, exp, pack P (fp16 single) ----
        float mx0 = -CUDART_INF_F, mx1 = -CUDART_INF_F;
        #pragma unroll
        for (int i = 0; i < 8; i++) {
            mx0 = fmaxf(mx0, fmaxf(s[i][0], s[i][1]));
            mx1 = fmaxf(mx1, fmaxf(s[i][2], s[i][3]));
        }
        mx0 = fmaxf(mx0, __shfl_xor_sync(0xffffffffu, mx0, 1));
        mx0 = fmaxf(mx0, __shfl_xor_sync(0xffffffffu, mx0, 2));
        mx1 = fmaxf(mx1, __shfl_xor_sync(0xffffffffu, mx1, 1));
        mx1 = fmaxf(mx1, __shfl_xor_sync(0xffffffffu, mx1, 2));

        float mN0 = fmaxf(m0, mx0);
        float mN1 = fmaxf(m1, mx1);
        float a0 = __expf(m0 - mN0);
        float a1 = __expf(m1 - mN1);
        m0 = mN0; m1 = mN1;
        l0 *= a0;  l1 *= a1;
        #pragma unroll
        for (int i = 0; i < 9; i++) {
            o[i][0] *= a0; o[i][1] *= a0;
            o[i][2] *= a1; o[i][3] *= a1;
        }

        uint32_t ph[4][4];
        #pragma unroll
        for (int u = 0; u < 4; u++) {
            float e00 = __expf(s[2 * u][0] - m0);
            float e01 = __expf(s[2 * u][1] - m0);
            float e02 = __expf(s[2 * u][2] - m1);
            float e03 = __expf(s[2 * u][3] - m1);
            float e10 = __expf(s[2 * u + 1][0] - m0);
            float e11 = __expf(s[2 * u + 1][1] - m0);
            float e12 = __expf(s[2 * u + 1][2] - m1);
            float e13 = __expf(s[2 * u + 1][3] - m1);
            l0 += (e00 + e01) + (e10 + e11);
            l1 += (e02 + e03) + (e12 + e13);
            ph[u][0] = pack2h(e00, e01);
            ph[u][1] = pack2h(e02, e03);
            ph[u][2] = pack2h(e10, e11);
            ph[u][3] = pack2h(e12, e13);
        }

        // ---- PV: O += Ph·Xh (single pass) ----
        #pragma unroll
        for (int kc2 = 0; kc2 < 4; kc2++) {
            #pragma unroll
            for (int dn2 = 0; dn2 < 4; dn2++) {
                uint32_t off = (16 * kc2 * SKW + 16 * dn2) * 2 + pv_off;
                uint32_t b0, b1, b2, b3;
                LDSM4T(b0, b1, b2, b3, sXh + off);
                MMA_F16(o[2 * dn2],     ph[kc2], b0, b1);
                MMA_F16(o[2 * dn2 + 1], ph[kc2], b2, b3);
            }
            {
                uint32_t off = (16 * kc2 * SKW) * 2 + pv2_off;
                uint32_t b0, b1;
                LDSM2T(b0, b1, sXh + off);
                MMA_F16(o[8], ph[kc2], b0, b1);
            }
        }
        __syncthreads();
    }

    // ---- epilogue: reduce l over quad, write (m, l) + unnormalized O ----
    l0 += __shfl_xor_sync(0xffffffffu, l0, 1);
    l0 += __shfl_xor_sync(0xffffffffu, l0, 2);
    l1 += __shfl_xor_sync(0xffffffffu, l1, 1);
    l1 += __shfl_xor_sync(0xffffffffu, l1, 2);
    if ((lane & 3) == 0) {
        g_ml[split * NQT + q0 + g]     = make_float2(m0, l0);
        g_ml[split * NQT + q0 + g + 8] = make_float2(m1, l1);
    }
    const size_t ob = (size_t)split * NQT;
    #pragma unroll
    for (int dn = 0; dn < 9; dn++) {
        int d0 = 8 * dn + 2 * t;
        if (d0 < D66) {
            *(float2*)(g_part + (ob + q0 + g)     * D66 + d0) = make_float2(o[dn][0], o[dn][1]);
            *(float2*)(g_part + (ob + q0 + g + 8) * D66 + d0) = make_float2(o[dn][2], o[dn][3]);
        }
    }
}

// ============================================================
// Kernel 3: combine splits (log-sum-exp merge)
// ============================================================
__global__ void __launch_bounds__(256)
combine_kernel(float* __restrict__ out) {
    const int q = blockIdx.x * 256 + threadIdx.x;
    float2 ml[SPLITS];
    float M = -CUDART_INF_F;
    #pragma unroll
    for (int s = 0; s < SPLITS; s++) {
        ml[s] = g_ml[s * NQT + q];
        M = fmaxf(M, ml[s].x);
    }
    float wgt[SPLITS];
    float l = 0.0f;
    #pragma unroll
    for (int s = 0; s < SPLITS; s++) {
        wgt[s] = __expf(ml[s].x - M);
        l += wgt[s] * ml[s].y;
    }
    float inv = 1.0f / l;
    #pragma unroll 3
    for (int c = 0; c < 33; c++) {
        float ax = 0.0f, ay = 0.0f;
        #pragma unroll
        for (int s = 0; s < SPLITS; s++) {
            float2 v = *(const float2*)(g_part + ((size_t)s * NQT + q) * D66 + 2 * c);
            ax = fmaf(wgt[s], v.x, ax);
            ay = fmaf(wgt[s], v.y, ay);
        }
        out[(size_t)q * D66 + 2 * c]     = ax * inv;
        out[(size_t)q * D66 + 2 * c + 1] = ay * inv;
    }
}

// ============================================================
extern "C" void kernel_launch(void* const* d_in, const int* in_sizes, int n_in,
                              void* d_out, int out_size) {
    const float* x     = (const float*)d_in[0];
    const float* query = (const float*)d_in[1];
    const float* Wk    = (const float*)d_in[2];
    const float* bk    = (const float*)d_in[3];
    float* out = (float*)d_out;

    const int smem_bytes = 2 * CHUNK_B;   // 67584
    cudaFuncSetAttribute(flash_kernel,
                         cudaFuncAttributeMaxDynamicSharedMemorySize, smem_bytes);

    prep_kernel<<<NK / 128, 128>>>(x, Wk, bk);
    flash_kernel<<<64 * SPLITS, 256, smem_bytes>>>(query);
    combine_kernel<<<NQT / 256, 256>>>(out);
}

// round 6
// speedup vs baseline: 11.5433x; 1.1143x over previous
#include <cuda_runtime.h>
#include <cuda_fp16.h>
#include <math_constants.h>
#include <cstdint>

#define D66     66
#define DP      72                 // padded dim (4x k16 + 1x k8)
#define NK      65536
#define NQT     8192
#define SPLITS  32
#define KSPLIT  (NK / SPLITS)      // 2048
#define CK      64
#define NCH     (KSPLIT / CK)      // 32 chunks per block
#define SKW     72                 // smem row pitch (fp16 elems); 144B rows, conflict-free
#define ABYTES  (CK * SKW * 2)     // 9216
#define CHUNK_B (2 * ABYTES)       // 18432 (Xh, Xl)
#define GROUPS  (2 * CK * 9)       // 1152 16B-groups per chunk

// static device scratch (no cudaMalloc)
__device__ __align__(16) __half g_x2[(size_t)2 * NK * DP];    // Xh, Xl  (18.9 MB)
__device__ __align__(16) __half g_qp[(size_t)2 * NQT * DP];   // q'h, q'l
__device__ float  g_part[(size_t)SPLITS * NQT * D66];         // 69 MB
__device__ float2 g_ml[SPLITS * NQT];

// ---------------- asm helpers ----------------
#define MMA16(dv, av, b0_, b1_)                                             \
    asm volatile("mma.sync.aligned.m16n8k16.row.col.f32.f16.f16.f32 "       \
                 "{%0,%1,%2,%3},{%4,%5,%6,%7},{%8,%9},{%0,%1,%2,%3};"       \
                 : "+f"(dv[0]), "+f"(dv[1]), "+f"(dv[2]), "+f"(dv[3])       \
                 : "r"(av[0]), "r"(av[1]), "r"(av[2]), "r"(av[3]),          \
                   "r"(b0_), "r"(b1_))

#define MMA8(dv, a0_, a1_, b0_)                                             \
    asm volatile("mma.sync.aligned.m16n8k8.row.col.f32.f16.f16.f32 "        \
                 "{%0,%1,%2,%3},{%4,%5},{%6},{%0,%1,%2,%3};"                \
                 : "+f"(dv[0]), "+f"(dv[1]), "+f"(dv[2]), "+f"(dv[3])       \
                 : "r"(a0_), "r"(a1_), "r"(b0_))

#define LDSM4(r0, r1, r2, r3, ad)                                           \
    asm volatile("ldmatrix.sync.aligned.m8n8.x4.shared.b16 {%0,%1,%2,%3},[%4];" \
                 : "=r"(r0), "=r"(r1), "=r"(r2), "=r"(r3) : "r"(ad))

#define LDSM2(r0, r1, ad)                                                   \
    asm volatile("ldmatrix.sync.aligned.m8n8.x2.shared.b16 {%0,%1},[%2];"   \
                 : "=r"(r0), "=r"(r1) : "r"(ad))

#define LDSM4T(r0, r1, r2, r3, ad)                                          \
    asm volatile("ldmatrix.sync.aligned.m8n8.x4.trans.shared.b16 {%0,%1,%2,%3},[%4];" \
                 : "=r"(r0), "=r"(r1), "=r"(r2), "=r"(r3) : "r"(ad))

#define LDSM2T(r0, r1, ad)                                                  \
    asm volatile("ldmatrix.sync.aligned.m8n8.x2.trans.shared.b16 {%0,%1},[%2];" \
                 : "=r"(r0), "=r"(r1) : "r"(ad))

__device__ __forceinline__ void cp16(uint32_t dst, const void* src) {
    asm volatile("cp.async.cg.shared.global [%0],[%1],16;" :: "r"(dst), "l"(src));
}
__device__ __forceinline__ void cpcommit() { asm volatile("cp.async.commit_group;"); }
__device__ __forceinline__ void cpwait1()  { asm volatile("cp.async.wait_group 1;"); }
__device__ __forceinline__ void cpwait0()  { asm volatile("cp.async.wait_group 0;"); }

__device__ __forceinline__ void split2h(float x, float y, uint32_t& hi, uint32_t& lo) {
    __half2 h = __floats2half2_rn(x, y);
    hi = *reinterpret_cast<uint32_t*>(&h);
    float rx = x - __low2float(h);
    float ry = y - __high2float(h);
    __half2 l = __floats2half2_rn(rx, ry);
    lo = *reinterpret_cast<uint32_t*>(&l);
}
__device__ __forceinline__ uint32_t pack2h(float x, float y) {
    __half2 h = __floats2half2_rn(x, y);
    return *reinterpret_cast<uint32_t*>(&h);
}

// ============================================================
// Kernel 1a: q' = Wk^T q per query row (bias cancels in softmax).
// ============================================================
__global__ void __launch_bounds__(128)
qprime_kernel(const float* __restrict__ query, const float* __restrict__ Wk) {
    __shared__ float sW[D66 * D66];
    const int tid = threadIdx.x;
    const int row = blockIdx.x * 128 + tid;
    for (int i = tid; i < D66 * D66; i += 128) sW[i] = Wk[i];
    __syncthreads();

    float qr[D66];
    const float2* qp = (const float2*)(query + (size_t)row * D66);
    #pragma unroll
    for (int c = 0; c < 33; c++) { float2 v = qp[c]; qr[2*c] = v.x; qr[2*c+1] = v.y; }

    __half* Qh = g_qp;
    __half* Ql = g_qp + (size_t)NQT * DP;
    const size_t rb = (size_t)row * DP;

    #pragma unroll 1
    for (int j = 0; j < D66; j += 2) {
        float a0 = 0.0f, a1 = 0.0f;
        #pragma unroll
        for (int d = 0; d < D66; d++) {
            a0 = fmaf(qr[d], sW[d * D66 + j], a0);
            a1 = fmaf(qr[d], sW[d * D66 + j + 1], a1);
        }
        uint32_t hi, lo;
        split2h(a0, a1, hi, lo);
        *(uint32_t*)(Qh + rb + j) = hi;
        *(uint32_t*)(Ql + rb + j) = lo;
    }
    #pragma unroll
    for (int c = 33; c < DP / 2; c++) {
        *(uint32_t*)(Qh + rb + 2 * c) = 0u;
        *(uint32_t*)(Ql + rb + 2 * c) = 0u;
    }
}

// ============================================================
// Kernel 1b: split x into Xh/Xl fp16, padded to DP=72
// ============================================================
__global__ void __launch_bounds__(256)
xsplit_kernel(const float* __restrict__ x) {
    const int n = blockIdx.x * 256 + threadIdx.x;
    __half* Xh = g_x2;
    __half* Xl = g_x2 + (size_t)NK * DP;
    const size_t rb = (size_t)n * DP;
    const float2* xp = (const float2*)(x + (size_t)n * D66);
    #pragma unroll
    for (int c = 0; c < 33; c++) {
        float2 v = xp[c];
        uint32_t hi, lo;
        split2h(v.x, v.y, hi, lo);
        *(uint32_t*)(Xh + rb + 2 * c) = hi;
        *(uint32_t*)(Xl + rb + 2 * c) = lo;
    }
    #pragma unroll
    for (int c = 33; c < DP / 2; c++) {
        *(uint32_t*)(Xh + rb + 2 * c) = 0u;
        *(uint32_t*)(Xl + rb + 2 * c) = 0u;
    }
}

// ============================================================
// Kernel 2: flash attention selector — 4 warps x 32 q-rows,
// scores = q'.x (3-pass fp16 hi/lo), PV single pass, online max.
// ============================================================
extern __shared__ __half smbuf[];

__global__ void __launch_bounds__(128)
flash_kernel() {
    const int tid  = threadIdx.x;
    const int lane = tid & 31;
    const int w    = tid >> 5;                 // 4 warps
    const int qtile = blockIdx.x & 63;
    const int split = blockIdx.x >> 6;         // 0..31
    const int q0w = qtile * 128 + w * 32;      // warp's 32 q rows
    const size_t k0 = (size_t)split * KSPLIT;

    const int g  = lane >> 2;
    const int t  = lane & 3;
    const int q8 = lane >> 3;
    const int r  = lane & 7;

    const uint32_t sbase = (uint32_t)__cvta_generic_to_shared(smbuf);

    // ---- q' fragments (resident): k16 x4 + k8 tail, hi/lo, 2 m-tiles ----
    uint32_t aqh[2][4][4], aql[2][4][4], aq8h[2][2], aq8l[2][2];
    {
        const __half* Qh = g_qp;
        const __half* Ql = g_qp + (size_t)NQT * DP;
        #pragma unroll
        for (int mt = 0; mt < 2; mt++) {
            const size_t r0 = (size_t)(q0w + 16 * mt + g) * DP;
            const size_t r1 = (size_t)(q0w + 16 * mt + g + 8) * DP;
            #pragma unroll
            for (int kc = 0; kc < 4; kc++) {
                int c0 = 16 * kc + 2 * t;
                aqh[mt][kc][0] = *(const uint32_t*)(Qh + r0 + c0);
                aqh[mt][kc][1] = *(const uint32_t*)(Qh + r1 + c0);
                aqh[mt][kc][2] = *(const uint32_t*)(Qh + r0 + c0 + 8);
                aqh[mt][kc][3] = *(const uint32_t*)(Qh + r1 + c0 + 8);
                aql[mt][kc][0] = *(const uint32_t*)(Ql + r0 + c0);
                aql[mt][kc][1] = *(const uint32_t*)(Ql + r1 + c0);
                aql[mt][kc][2] = *(const uint32_t*)(Ql + r0 + c0 + 8);
                aql[mt][kc][3] = *(const uint32_t*)(Ql + r1 + c0 + 8);
            }
            int c8 = 64 + 2 * t;
            aq8h[mt][0] = *(const uint32_t*)(Qh + r0 + c8);
            aq8h[mt][1] = *(const uint32_t*)(Qh + r1 + c8);
            aq8l[mt][0] = *(const uint32_t*)(Ql + r0 + c8);
            aq8l[mt][1] = *(const uint32_t*)(Ql + r1 + c8);
        }
    }

    // lane-constant ldmatrix offsets (bytes)
    const uint32_t qk_off  = ((8 * (q8 >> 1) + r) * SKW + 8 * (q8 & 1)) * 2;
    const uint32_t qk8_off = ((8 * (q8 & 1) + r) * SKW + 64) * 2;
    const uint32_t pv_off  = ((8 * (q8 & 1) + r) * SKW + 8 * (q8 >> 1)) * 2;
    const uint32_t pv2_off = ((8 * (q8 & 1) + r) * SKW + 64) * 2;

    float o[2][9][4];
    #pragma unroll
    for (int mt = 0; mt < 2; mt++)
        #pragma unroll
        for (int i = 0; i < 9; i++)
            #pragma unroll
            for (int c = 0; c < 4; c++) o[mt][i][c] = 0.0f;
    float m[4] = {-1e30f, -1e30f, -1e30f, -1e30f};
    float l[4] = {0.0f, 0.0f, 0.0f, 0.0f};

    #define PREFETCH(CH)                                                          \
    do {                                                                          \
        const size_t kb = k0 + (size_t)(CH) * CK;                                 \
        const uint32_t bb = sbase + ((CH) & 1) * CHUNK_B;                         \
        _Pragma("unroll")                                                         \
        for (int jj = 0; jj < 9; jj++) {                                          \
            int j = tid + jj * 128;                                               \
            int arr = j / 576;                                                    \
            int rem = j - arr * 576;                                              \
            int row = rem / 9;                                                    \
            int cc  = rem - row * 9;                                              \
            const __half* src = g_x2 + (size_t)arr * ((size_t)NK * DP)            \
                                + (kb + row) * DP + cc * 8;                       \
            uint32_t dst = bb + arr * ABYTES + (row * SKW + cc * 8) * 2;          \
            cp16(dst, src);                                                       \
        }                                                                         \
    } while (0)

    PREFETCH(0); cpcommit();

    for (int ch = 0; ch < NCH; ch++) {
        if (ch + 1 < NCH) { PREFETCH(ch + 1); cpcommit(); cpwait1(); }
        else              { cpwait0(); }
        __syncthreads();

        const uint32_t sXh = sbase + (ch & 1) * CHUNK_B;
        const uint32_t sXl = sXh + ABYTES;

        // ---- QK: S = q'h.Xh + q'h.Xl + q'l.Xh ----
        float s[2][8][4];
        #pragma unroll
        for (int mt = 0; mt < 2; mt++)
            #pragma unroll
            for (int i = 0; i < 8; i++)
                #pragma unroll
                for (int c = 0; c < 4; c++) s[mt][i][c] = 0.0f;

        #pragma unroll
        for (int kc = 0; kc < 4; kc++) {
            #pragma unroll
            for (int jn2 = 0; jn2 < 4; jn2++) {
                uint32_t off = (16 * jn2 * SKW + 16 * kc) * 2 + qk_off;
                uint32_t bh0, bh1, bh2, bh3, bl0, bl1, bl2, bl3;
                LDSM4(bh0, bh1, bh2, bh3, sXh + off);
                LDSM4(bl0, bl1, bl2, bl3, sXl + off);
                #pragma unroll
                for (int mt = 0; mt < 2; mt++) {
                    MMA16(s[mt][2 * jn2],     aqh[mt][kc], bh0, bh1);
                    MMA16(s[mt][2 * jn2],     aqh[mt][kc], bl0, bl1);
                    MMA16(s[mt][2 * jn2],     aql[mt][kc], bh0, bh1);
                    MMA16(s[mt][2 * jn2 + 1], aqh[mt][kc], bh2, bh3);
                    MMA16(s[mt][2 * jn2 + 1], aqh[mt][kc], bl2, bl3);
                    MMA16(s[mt][2 * jn2 + 1], aql[mt][kc], bh2, bh3);
                }
            }
        }
        // k8 tail (dims 64..71; 66+ are zero)
        #pragma unroll
        for (int jn2 = 0; jn2 < 4; jn2++) {
            uint32_t off = (16 * jn2 * SKW) * 2 + qk8_off;
            uint32_t bh0, bh1, bl0, bl1;
            LDSM2(bh0, bh1, sXh + off);
            LDSM2(bl0, bl1, sXl + off);
            #pragma unroll
            for (int mt = 0; mt < 2; mt++) {
                MMA8(s[mt][2 * jn2],     aq8h[mt][0], aq8h[mt][1], bh0);
                MMA8(s[mt][2 * jn2],     aq8h[mt][0], aq8h[mt][1], bl0);
                MMA8(s[mt][2 * jn2],     aq8l[mt][0], aq8l[mt][1], bh0);
                MMA8(s[mt][2 * jn2 + 1], aq8h[mt][0], aq8h[mt][1], bh1);
                MMA8(s[mt][2 * jn2 + 1], aq8h[mt][0], aq8h[mt][1], bl1);
                MMA8(s[mt][2 * jn2 + 1], aq8l[mt][0], aq8l[mt][1], bh1);
            }
        }

        // ---- online softmax + P pack ----
        uint32_t ph[2][4][4];
        #pragma unroll
        for (int mt = 0; mt < 2; mt++) {
            float mx0 = -1e30f, mx1 = -1e30f;
            #pragma unroll
            for (int i = 0; i < 8; i++) {
                mx0 = fmaxf(mx0, fmaxf(s[mt][i][0], s[mt][i][1]));
                mx1 = fmaxf(mx1, fmaxf(s[mt][i][2], s[mt][i][3]));
            }
            mx0 = fmaxf(mx0, __shfl_xor_sync(0xffffffffu, mx0, 1));
            mx0 = fmaxf(mx0, __shfl_xor_sync(0xffffffffu, mx0, 2));
            mx1 = fmaxf(mx1, __shfl_xor_sync(0xffffffffu, mx1, 1));
            mx1 = fmaxf(mx1, __shfl_xor_sync(0xffffffffu, mx1, 2));

            float mN0 = fmaxf(m[2 * mt], mx0);
            float mN1 = fmaxf(m[2 * mt + 1], mx1);
            float a0 = __expf(m[2 * mt] - mN0);
            float a1 = __expf(m[2 * mt + 1] - mN1);
            m[2 * mt] = mN0; m[2 * mt + 1] = mN1;
            l[2 * mt] *= a0; l[2 * mt + 1] *= a1;
            #pragma unroll
            for (int i = 0; i < 9; i++) {
                o[mt][i][0] *= a0; o[mt][i][1] *= a0;
                o[mt][i][2] *= a1; o[mt][i][3] *= a1;
            }
            #pragma unroll
            for (int u = 0; u < 4; u++) {
                float e00 = __expf(s[mt][2 * u][0] - mN0);
                float e01 = __expf(s[mt][2 * u][1] - mN0);
                float e02 = __expf(s[mt][2 * u][2] - mN1);
                float e03 = __expf(s[mt][2 * u][3] - mN1);
                float e10 = __expf(s[mt][2 * u + 1][0] - mN0);
                float e11 = __expf(s[mt][2 * u + 1][1] - mN0);
                float e12 = __expf(s[mt][2 * u + 1][2] - mN1);
                float e13 = __expf(s[mt][2 * u + 1][3] - mN1);
                l[2 * mt]     += (e00 + e01) + (e10 + e11);
                l[2 * mt + 1] += (e02 + e03) + (e12 + e13);
                ph[mt][u][0] = pack2h(e00, e01);
                ph[mt][u][1] = pack2h(e02, e03);
                ph[mt][u][2] = pack2h(e10, e11);
                ph[mt][u][3] = pack2h(e12, e13);
            }
        }

        // ---- PV: O += P.Xh ----
        #pragma unroll
        for (int kc2 = 0; kc2 < 4; kc2++) {
            #pragma unroll
            for (int dn2 = 0; dn2 < 4; dn2++) {
                uint32_t off = (16 * kc2 * SKW + 16 * dn2) * 2 + pv_off;
                uint32_t b0, b1, b2, b3;
                LDSM4T(b0, b1, b2, b3, sXh + off);
                #pragma unroll
                for (int mt = 0; mt < 2; mt++) {
                    MMA16(o[mt][2 * dn2],     ph[mt][kc2], b0, b1);
                    MMA16(o[mt][2 * dn2 + 1], ph[mt][kc2], b2, b3);
                }
            }
            {
                uint32_t off = (16 * kc2 * SKW) * 2 + pv2_off;
                uint32_t b0, b1;
                LDSM2T(b0, b1, sXh + off);
                #pragma unroll
                for (int mt = 0; mt < 2; mt++)
                    MMA16(o[mt][8], ph[mt][kc2], b0, b1);
            }
        }
        __syncthreads();
    }

    // ---- epilogue ----
    #pragma unroll
    for (int i = 0; i < 4; i++) {
        l[i] += __shfl_xor_sync(0xffffffffu, l[i], 1);
        l[i] += __shfl_xor_sync(0xffffffffu, l[i], 2);
    }
    if ((lane & 3) == 0) {
        #pragma unroll
        for (int mt = 0; mt < 2; mt++) {
            g_ml[split * NQT + q0w + 16 * mt + g]     = make_float2(m[2*mt],   l[2*mt]);
            g_ml[split * NQT + q0w + 16 * mt + g + 8] = make_float2(m[2*mt+1], l[2*mt+1]);
        }
    }
    const size_t ob = (size_t)split * NQT;
    #pragma unroll
    for (int mt = 0; mt < 2; mt++) {
        #pragma unroll
        for (int dn = 0; dn < 9; dn++) {
            int d0 = 8 * dn + 2 * t;
            if (d0 < D66) {
                *(float2*)(g_part + (ob + q0w + 16*mt + g)     * D66 + d0) =
                    make_float2(o[mt][dn][0], o[mt][dn][1]);
                *(float2*)(g_part + (ob + q0w + 16*mt + g + 8) * D66 + d0) =
                    make_float2(o[mt][dn][2], o[mt][dn][3]);
            }
        }
    }
}

// ============================================================
// Kernel 3: combine splits (LSE merge over 32)
// ============================================================
__global__ void __launch_bounds__(256)
combine_kernel(float* __restrict__ out) {
    const int q = blockIdx.x * 256 + threadIdx.x;
    float M = -1e30f;
    float mx[SPLITS], lx[SPLITS];
    #pragma unroll
    for (int s = 0; s < SPLITS; s++) {
        float2 v = g_ml[s * NQT + q];
        mx[s] = v.x; lx[s] = v.y;
        M = fmaxf(M, v.x);
    }
    float wgt[SPLITS];
    float l = 0.0f;
    #pragma unroll
    for (int s = 0; s < SPLITS; s++) {
        wgt[s] = __expf(mx[s] - M);
        l += wgt[s] * lx[s];
    }
    float inv = 1.0f / l;
    #pragma unroll 3
    for (int c = 0; c < 33; c++) {
        float ax = 0.0f, ay = 0.0f;
        #pragma unroll
        for (int s = 0; s < SPLITS; s++) {
            float2 v = *(const float2*)(g_part + ((size_t)s * NQT + q) * D66 + 2 * c);
            ax = fmaf(wgt[s], v.x, ax);
            ay = fmaf(wgt[s], v.y, ay);
        }
        out[(size_t)q * D66 + 2 * c]     = ax * inv;
        out[(size_t)q * D66 + 2 * c + 1] = ay * inv;
    }
}

// ============================================================
extern "C" void kernel_launch(void* const* d_in, const int* in_sizes, int n_in,
                              void* d_out, int out_size) {
    const float* x     = (const float*)d_in[0];
    const float* query = (const float*)d_in[1];
    const float* Wk    = (const float*)d_in[2];
    // bk unused: q.b is constant per softmax row and cancels.
    float* out = (float*)d_out;

    const int smem_bytes = 2 * CHUNK_B;   // 36864
    cudaFuncSetAttribute(flash_kernel,
                         cudaFuncAttributeMaxDynamicSharedMemorySize, smem_bytes);

    qprime_kernel<<<NQT / 128, 128>>>(query, Wk);
    xsplit_kernel<<<NK / 256, 256>>>(x);
    flash_kernel<<<64 * SPLITS, 128, smem_bytes>>>();
    combine_kernel<<<NQT / 256, 256>>>(out);
}

// round 7
// speedup vs baseline: 12.6770x; 1.0982x over previous
#include <cuda_runtime.h>
#include <cuda_fp16.h>
#include <cstdint>

#define D66     66
#define DP      72                 // padded dim (4x k16 + 1x k8)
#define NK      65536
#define NQT     8192
#define SPLITS  16
#define KSPLIT  (NK / SPLITS)      // 4096
#define CK      64
#define NCH     (KSPLIT / CK)      // 64 chunks per block
#define SKW     72                 // smem row pitch (fp16 elems); 144B rows
#define ABYTES  (CK * SKW * 2)     // 9216
#define CHUNK_B (2 * ABYTES)       // 18432 (Xh, Xl)

// static device scratch (no cudaMalloc)
__device__ __align__(16) __half g_x2[(size_t)2 * NK * DP];    // Xh, Xl
__device__ __align__(16) __half g_qp[(size_t)2 * NQT * DP];   // q'h, q'l
__device__ float  g_part[(size_t)SPLITS * NQT * D66];         // 34.6 MB
__device__ float2 g_ml[SPLITS * NQT];

// ---------------- asm helpers ----------------
#define MMA16(dv, av, b0_, b1_)                                             \
    asm volatile("mma.sync.aligned.m16n8k16.row.col.f32.f16.f16.f32 "       \
                 "{%0,%1,%2,%3},{%4,%5,%6,%7},{%8,%9},{%0,%1,%2,%3};"       \
                 : "+f"(dv[0]), "+f"(dv[1]), "+f"(dv[2]), "+f"(dv[3])       \
                 : "r"(av[0]), "r"(av[1]), "r"(av[2]), "r"(av[3]),          \
                   "r"(b0_), "r"(b1_))

#define MMA8(dv, a0_, a1_, b0_)                                             \
    asm volatile("mma.sync.aligned.m16n8k8.row.col.f32.f16.f16.f32 "        \
                 "{%0,%1,%2,%3},{%4,%5},{%6},{%0,%1,%2,%3};"                \
                 : "+f"(dv[0]), "+f"(dv[1]), "+f"(dv[2]), "+f"(dv[3])       \
                 : "r"(a0_), "r"(a1_), "r"(b0_))

#define LDSM4(r0, r1, r2, r3, ad)                                           \
    asm volatile("ldmatrix.sync.aligned.m8n8.x4.shared.b16 {%0,%1,%2,%3},[%4];" \
                 : "=r"(r0), "=r"(r1), "=r"(r2), "=r"(r3) : "r"(ad))

#define LDSM2(r0, r1, ad)                                                   \
    asm volatile("ldmatrix.sync.aligned.m8n8.x2.shared.b16 {%0,%1},[%2];"   \
                 : "=r"(r0), "=r"(r1) : "r"(ad))

#define LDSM4T(r0, r1, r2, r3, ad)                                          \
    asm volatile("ldmatrix.sync.aligned.m8n8.x4.trans.shared.b16 {%0,%1,%2,%3},[%4];" \
                 : "=r"(r0), "=r"(r1), "=r"(r2), "=r"(r3) : "r"(ad))

#define LDSM2T(r0, r1, ad)                                                  \
    asm volatile("ldmatrix.sync.aligned.m8n8.x2.trans.shared.b16 {%0,%1},[%2];" \
                 : "=r"(r0), "=r"(r1) : "r"(ad))

__device__ __forceinline__ void cp16(uint32_t dst, const void* src) {
    asm volatile("cp.async.cg.shared.global [%0],[%1],16;" :: "r"(dst), "l"(src));
}
__device__ __forceinline__ void cpcommit() { asm volatile("cp.async.commit_group;"); }
__device__ __forceinline__ void cpwait1()  { asm volatile("cp.async.wait_group 1;"); }
__device__ __forceinline__ void cpwait0()  { asm volatile("cp.async.wait_group 0;"); }

__device__ __forceinline__ void split2h(float x, float y, uint32_t& hi, uint32_t& lo) {
    __half2 h = __floats2half2_rn(x, y);
    hi = *reinterpret_cast<uint32_t*>(&h);
    float rx = x - __low2float(h);
    float ry = y - __high2float(h);
    __half2 l = __floats2half2_rn(rx, ry);
    lo = *reinterpret_cast<uint32_t*>(&l);
}
__device__ __forceinline__ uint32_t pack2h(float x, float y) {
    __half2 h = __floats2half2_rn(x, y);
    return *reinterpret_cast<uint32_t*>(&h);
}
// packed fp16x2 exp2 (one MUFU for two values)
__device__ __forceinline__ uint32_t ex2h2(uint32_t a) {
    uint32_t d;
    asm("ex2.approx.f16x2 %0, %1;" : "=r"(d) : "r"(a));
    return d;
}

#define L2E 1.44269504f

// ============================================================
// Kernel 1a: q' = Wk^T q (bias cancels in softmax)
// ============================================================
__global__ void __launch_bounds__(128)
qprime_kernel(const float* __restrict__ query, const float* __restrict__ Wk) {
    __shared__ float sW[D66 * D66];
    const int tid = threadIdx.x;
    const int row = blockIdx.x * 128 + tid;
    for (int i = tid; i < D66 * D66; i += 128) sW[i] = Wk[i];
    __syncthreads();

    float qr[D66];
    const float2* qp = (const float2*)(query + (size_t)row * D66);
    #pragma unroll
    for (int c = 0; c < 33; c++) { float2 v = qp[c]; qr[2*c] = v.x; qr[2*c+1] = v.y; }

    __half* Qh = g_qp;
    __half* Ql = g_qp + (size_t)NQT * DP;
    const size_t rb = (size_t)row * DP;

    #pragma unroll 1
    for (int j = 0; j < D66; j += 2) {
        float a0 = 0.0f, a1 = 0.0f;
        #pragma unroll
        for (int d = 0; d < D66; d++) {
            a0 = fmaf(qr[d], sW[d * D66 + j], a0);
            a1 = fmaf(qr[d], sW[d * D66 + j + 1], a1);
        }
        uint32_t hi, lo;
        split2h(a0, a1, hi, lo);
        *(uint32_t*)(Qh + rb + j) = hi;
        *(uint32_t*)(Ql + rb + j) = lo;
    }
    #pragma unroll
    for (int c = 33; c < DP / 2; c++) {
        *(uint32_t*)(Qh + rb + 2 * c) = 0u;
        *(uint32_t*)(Ql + rb + 2 * c) = 0u;
    }
}

// ============================================================
// Kernel 1b: split x into Xh/Xl fp16, padded to DP=72
// ============================================================
__global__ void __launch_bounds__(256)
xsplit_kernel(const float* __restrict__ x) {
    const int n = blockIdx.x * 256 + threadIdx.x;
    __half* Xh = g_x2;
    __half* Xl = g_x2 + (size_t)NK * DP;
    const size_t rb = (size_t)n * DP;
    const float2* xp = (const float2*)(x + (size_t)n * D66);
    #pragma unroll
    for (int c = 0; c < 33; c++) {
        float2 v = xp[c];
        uint32_t hi, lo;
        split2h(v.x, v.y, hi, lo);
        *(uint32_t*)(Xh + rb + 2 * c) = hi;
        *(uint32_t*)(Xl + rb + 2 * c) = lo;
    }
    #pragma unroll
    for (int c = 33; c < DP / 2; c++) {
        *(uint32_t*)(Xh + rb + 2 * c) = 0u;
        *(uint32_t*)(Xl + rb + 2 * c) = 0u;
    }
}

// ============================================================
// Kernel 2: flash attention selector — 4 warps x 32 q-rows
// ============================================================
extern __shared__ __half smbuf[];

__global__ void __launch_bounds__(128)
flash_kernel() {
    const int tid  = threadIdx.x;
    const int lane = tid & 31;
    const int w    = tid >> 5;
    const int qtile = blockIdx.x & 63;
    const int split = blockIdx.x >> 6;         // 0..15
    const int q0w = qtile * 128 + w * 32;
    const size_t k0 = (size_t)split * KSPLIT;

    const int g  = lane >> 2;
    const int t  = lane & 3;
    const int q8 = lane >> 3;
    const int r  = lane & 7;

    const uint32_t sbase = (uint32_t)__cvta_generic_to_shared(smbuf);

    // ---- q' fragments (resident) ----
    uint32_t aqh[2][4][4], aql[2][4][4], aq8h[2][2], aq8l[2][2];
    {
        const __half* Qh = g_qp;
        const __half* Ql = g_qp + (size_t)NQT * DP;
        #pragma unroll
        for (int mt = 0; mt < 2; mt++) {
            const size_t r0 = (size_t)(q0w + 16 * mt + g) * DP;
            const size_t r1 = (size_t)(q0w + 16 * mt + g + 8) * DP;
            #pragma unroll
            for (int kc = 0; kc < 4; kc++) {
                int c0 = 16 * kc + 2 * t;
                aqh[mt][kc][0] = *(const uint32_t*)(Qh + r0 + c0);
                aqh[mt][kc][1] = *(const uint32_t*)(Qh + r1 + c0);
                aqh[mt][kc][2] = *(const uint32_t*)(Qh + r0 + c0 + 8);
                aqh[mt][kc][3] = *(const uint32_t*)(Qh + r1 + c0 + 8);
                aql[mt][kc][0] = *(const uint32_t*)(Ql + r0 + c0);
                aql[mt][kc][1] = *(const uint32_t*)(Ql + r1 + c0);
                aql[mt][kc][2] = *(const uint32_t*)(Ql + r0 + c0 + 8);
                aql[mt][kc][3] = *(const uint32_t*)(Ql + r1 + c0 + 8);
            }
            int c8 = 64 + 2 * t;
            aq8h[mt][0] = *(const uint32_t*)(Qh + r0 + c8);
            aq8h[mt][1] = *(const uint32_t*)(Qh + r1 + c8);
            aq8l[mt][0] = *(const uint32_t*)(Ql + r0 + c8);
            aq8l[mt][1] = *(const uint32_t*)(Ql + r1 + c8);
        }
    }

    const uint32_t qk_off  = ((8 * (q8 >> 1) + r) * SKW + 8 * (q8 & 1)) * 2;
    const uint32_t qk8_off = ((8 * (q8 & 1) + r) * SKW + 64) * 2;
    const uint32_t pv_off  = ((8 * (q8 & 1) + r) * SKW + 8 * (q8 >> 1)) * 2;
    const uint32_t pv2_off = ((8 * (q8 & 1) + r) * SKW + 64) * 2;

    float o[2][9][4];
    #pragma unroll
    for (int mt = 0; mt < 2; mt++)
        #pragma unroll
        for (int i = 0; i < 9; i++)
            #pragma unroll
            for (int c = 0; c < 4; c++) o[mt][i][c] = 0.0f;
    float m[4] = {-1e30f, -1e30f, -1e30f, -1e30f};
    float l[4] = {0.0f, 0.0f, 0.0f, 0.0f};

    #define PREFETCH(CH)                                                          \
    do {                                                                          \
        const size_t kb = k0 + (size_t)(CH) * CK;                                 \
        const uint32_t bb = sbase + ((CH) & 1) * CHUNK_B;                         \
        _Pragma("unroll")                                                         \
        for (int jj = 0; jj < 9; jj++) {                                          \
            int j = tid + jj * 128;                                               \
            int arr = j / 576;                                                    \
            int rem = j - arr * 576;                                              \
            int row = rem / 9;                                                    \
            int cc  = rem - row * 9;                                              \
            const __half* src = g_x2 + (size_t)arr * ((size_t)NK * DP)            \
                                + (kb + row) * DP + cc * 8;                       \
            uint32_t dst = bb + arr * ABYTES + (row * SKW + cc * 8) * 2;          \
            cp16(dst, src);                                                       \
        }                                                                         \
    } while (0)

    PREFETCH(0); cpcommit();

    for (int ch = 0; ch < NCH; ch++) {
        if (ch + 1 < NCH) { PREFETCH(ch + 1); cpcommit(); cpwait1(); }
        else              { cpwait0(); }
        __syncthreads();

        const uint32_t sXh = sbase + (ch & 1) * CHUNK_B;
        const uint32_t sXl = sXh + ABYTES;

        // ---- QK: S = q'h.Xh + q'h.Xl + q'l.Xh ----
        float s[2][8][4];
        #pragma unroll
        for (int mt = 0; mt < 2; mt++)
            #pragma unroll
            for (int i = 0; i < 8; i++)
                #pragma unroll
                for (int c = 0; c < 4; c++) s[mt][i][c] = 0.0f;

        #pragma unroll
        for (int kc = 0; kc < 4; kc++) {
            #pragma unroll
            for (int jn2 = 0; jn2 < 4; jn2++) {
                uint32_t off = (16 * jn2 * SKW + 16 * kc) * 2 + qk_off;
                uint32_t bh0, bh1, bh2, bh3, bl0, bl1, bl2, bl3;
                LDSM4(bh0, bh1, bh2, bh3, sXh + off);
                LDSM4(bl0, bl1, bl2, bl3, sXl + off);
                #pragma unroll
                for (int mt = 0; mt < 2; mt++) {
                    MMA16(s[mt][2 * jn2],     aqh[mt][kc], bh0, bh1);
                    MMA16(s[mt][2 * jn2],     aqh[mt][kc], bl0, bl1);
                    MMA16(s[mt][2 * jn2],     aql[mt][kc], bh0, bh1);
                    MMA16(s[mt][2 * jn2 + 1], aqh[mt][kc], bh2, bh3);
                    MMA16(s[mt][2 * jn2 + 1], aqh[mt][kc], bl2, bl3);
                    MMA16(s[mt][2 * jn2 + 1], aql[mt][kc], bh2, bh3);
                }
            }
        }
        #pragma unroll
        for (int jn2 = 0; jn2 < 4; jn2++) {
            uint32_t off = (16 * jn2 * SKW) * 2 + qk8_off;
            uint32_t bh0, bh1, bl0, bl1;
            LDSM2(bh0, bh1, sXh + off);
            LDSM2(bl0, bl1, sXl + off);
            #pragma unroll
            for (int mt = 0; mt < 2; mt++) {
                MMA8(s[mt][2 * jn2],     aq8h[mt][0], aq8h[mt][1], bh0);
                MMA8(s[mt][2 * jn2],     aq8h[mt][0], aq8h[mt][1], bl0);
                MMA8(s[mt][2 * jn2],     aq8l[mt][0], aq8l[mt][1], bh0);
                MMA8(s[mt][2 * jn2 + 1], aq8h[mt][0], aq8h[mt][1], bh1);
                MMA8(s[mt][2 * jn2 + 1], aq8h[mt][0], aq8h[mt][1], bl1);
                MMA8(s[mt][2 * jn2 + 1], aq8l[mt][0], aq8l[mt][1], bh1);
            }
        }

        // ---- online softmax: f16x2 exp2, alpha-skip, half2 l-accum ----
        uint32_t ph[2][4][4];
        #pragma unroll
        for (int mt = 0; mt < 2; mt++) {
            float mx0 = -1e30f, mx1 = -1e30f;
            #pragma unroll
            for (int i = 0; i < 8; i++) {
                mx0 = fmaxf(mx0, fmaxf(s[mt][i][0], s[mt][i][1]));
                mx1 = fmaxf(mx1, fmaxf(s[mt][i][2], s[mt][i][3]));
            }
            mx0 = fmaxf(mx0, __shfl_xor_sync(0xffffffffu, mx0, 1));
            mx0 = fmaxf(mx0, __shfl_xor_sync(0xffffffffu, mx0, 2));
            mx1 = fmaxf(mx1, __shfl_xor_sync(0xffffffffu, mx1, 1));
            mx1 = fmaxf(mx1, __shfl_xor_sync(0xffffffffu, mx1, 2));

            float mN0 = fmaxf(m[2 * mt], mx0);
            float mN1 = fmaxf(m[2 * mt + 1], mx1);
            bool nochg = (mN0 == m[2 * mt]) && (mN1 == m[2 * mt + 1]);
            if (!__all_sync(0xffffffffu, nochg)) {
                float a0 = __expf(m[2 * mt] - mN0);
                float a1 = __expf(m[2 * mt + 1] - mN1);
                l[2 * mt] *= a0; l[2 * mt + 1] *= a1;
                #pragma unroll
                for (int i = 0; i < 9; i++) {
                    o[mt][i][0] *= a0; o[mt][i][1] *= a0;
                    o[mt][i][2] *= a1; o[mt][i][3] *= a1;
                }
                m[2 * mt] = mN0; m[2 * mt + 1] = mN1;
            }
            const float mL0 = mN0 * L2E;
            const float mL1 = mN1 * L2E;

            __half2 lA2 = __floats2half2_rn(0.f, 0.f);
            __half2 lB2 = __floats2half2_rn(0.f, 0.f);
            #pragma unroll
            for (int u = 0; u < 4; u++) {
                ph[mt][u][0] = ex2h2(pack2h(fmaf(s[mt][2*u][0],   L2E, -mL0),
                                            fmaf(s[mt][2*u][1],   L2E, -mL0)));
                ph[mt][u][1] = ex2h2(pack2h(fmaf(s[mt][2*u][2],   L2E, -mL1),
                                            fmaf(s[mt][2*u][3],   L2E, -mL1)));
                ph[mt][u][2] = ex2h2(pack2h(fmaf(s[mt][2*u+1][0], L2E, -mL0),
                                            fmaf(s[mt][2*u+1][1], L2E, -mL0)));
                ph[mt][u][3] = ex2h2(pack2h(fmaf(s[mt][2*u+1][2], L2E, -mL1),
                                            fmaf(s[mt][2*u+1][3], L2E, -mL1)));
                lA2 = __hadd2(lA2, *reinterpret_cast<__half2*>(&ph[mt][u][0]));
                lA2 = __hadd2(lA2, *reinterpret_cast<__half2*>(&ph[mt][u][2]));
                lB2 = __hadd2(lB2, *reinterpret_cast<__half2*>(&ph[mt][u][1]));
                lB2 = __hadd2(lB2, *reinterpret_cast<__half2*>(&ph[mt][u][3]));
            }
            float2 va = __half22float2(lA2);
            float2 vb = __half22float2(lB2);
            l[2 * mt]     += va.x + va.y;
            l[2 * mt + 1] += vb.x + vb.y;
        }

        // ---- PV: O += P.Xh ----
        #pragma unroll
        for (int kc2 = 0; kc2 < 4; kc2++) {
            #pragma unroll
            for (int dn2 = 0; dn2 < 4; dn2++) {
                uint32_t off = (16 * kc2 * SKW + 16 * dn2) * 2 + pv_off;
                uint32_t b0, b1, b2, b3;
                LDSM4T(b0, b1, b2, b3, sXh + off);
                #pragma unroll
                for (int mt = 0; mt < 2; mt++) {
                    MMA16(o[mt][2 * dn2],     ph[mt][kc2], b0, b1);
                    MMA16(o[mt][2 * dn2 + 1], ph[mt][kc2], b2, b3);
                }
            }
            {
                uint32_t off = (16 * kc2 * SKW) * 2 + pv2_off;
                uint32_t b0, b1;
                LDSM2T(b0, b1, sXh + off);
                #pragma unroll
                for (int mt = 0; mt < 2; mt++)
                    MMA16(o[mt][8], ph[mt][kc2], b0, b1);
            }
        }
        __syncthreads();
    }

    // ---- epilogue ----
    #pragma unroll
    for (int i = 0; i < 4; i++) {
        l[i] += __shfl_xor_sync(0xffffffffu, l[i], 1);
        l[i] += __shfl_xor_sync(0xffffffffu, l[i], 2);
    }
    if ((lane & 3) == 0) {
        #pragma unroll
        for (int mt = 0; mt < 2; mt++) {
            g_ml[split * NQT + q0w + 16 * mt + g]     = make_float2(m[2*mt],   l[2*mt]);
            g_ml[split * NQT + q0w + 16 * mt + g + 8] = make_float2(m[2*mt+1], l[2*mt+1]);
        }
    }
    const size_t ob = (size_t)split * NQT;
    #pragma unroll
    for (int mt = 0; mt < 2; mt++) {
        #pragma unroll
        for (int dn = 0; dn < 9; dn++) {
            int d0 = 8 * dn + 2 * t;
            if (d0 < D66) {
                *(float2*)(g_part + (ob + q0w + 16*mt + g)     * D66 + d0) =
                    make_float2(o[mt][dn][0], o[mt][dn][1]);
                *(float2*)(g_part + (ob + q0w + 16*mt + g + 8) * D66 + d0) =
                    make_float2(o[mt][dn][2], o[mt][dn][3]);
            }
        }
    }
}

// ============================================================
// Kernel 3: combine — 4 threads per query, LSE merge over 16
// ============================================================
__global__ void __launch_bounds__(256)
combine_kernel(float* __restrict__ out) {
    const int tid = threadIdx.x;
    const int part = tid & 3;
    const int q = blockIdx.x * 64 + (tid >> 2);

    float M = -1e30f;
    float mx[SPLITS], lx[SPLITS];
    #pragma unroll
    for (int s = 0; s < SPLITS; s++) {
        float2 v = g_ml[s * NQT + q];
        mx[s] = v.x; lx[s] = v.y;
        M = fmaxf(M, v.x);
    }
    float wgt[SPLITS];
    float l = 0.0f;
    #pragma unroll
    for (int s = 0; s < SPLITS; s++) {
        wgt[s] = __expf(mx[s] - M);
        l += wgt[s] * lx[s];
    }
    float inv = 1.0f / l;

    #pragma unroll
    for (int i = 0; i < 9; i++) {
        int pr = part * 9 + i;          // d-pair index, 0..35
        if (pr < 33) {
            float ax = 0.0f, ay = 0.0f;
            #pragma unroll
            for (int s = 0; s < SPLITS; s++) {
                float2 v = *(const float2*)(g_part + ((size_t)s * NQT + q) * D66 + 2 * pr);
                ax = fmaf(wgt[s], v.x, ax);
                ay = fmaf(wgt[s], v.y, ay);
            }
            out[(size_t)q * D66 + 2 * pr]     = ax * inv;
            out[(size_t)q * D66 + 2 * pr + 1] = ay * inv;
        }
    }
}

// ============================================================
extern "C" void kernel_launch(void* const* d_in, const int* in_sizes, int n_in,
                              void* d_out, int out_size) {
    const float* x     = (const float*)d_in[0];
    const float* query = (const float*)d_in[1];
    const float* Wk    = (const float*)d_in[2];
    // bk unused: q.b cancels in softmax
    float* out = (float*)d_out;

    const int smem_bytes = 2 * CHUNK_B;   // 36864
    cudaFuncSetAttribute(flash_kernel,
                         cudaFuncAttributeMaxDynamicSharedMemorySize, smem_bytes);

    qprime_kernel<<<NQT / 128, 128>>>(query, Wk);
    xsplit_kernel<<<NK / 256, 256>>>(x);
    flash_kernel<<<64 * SPLITS, 128, smem_bytes>>>();
    combine_kernel<<<NQT / 64, 256>>>(out);
}

// round 8
// speedup vs baseline: 18.1280x; 1.4300x over previous
#include <cuda_runtime.h>
#include <cuda_fp16.h>
#include <cstdint>

#define D66     66
#define DP      72                 // padded dim (4x k16 + 1x k8)
#define NK      65536
#define NQT     8192
#define SPLITS  18
#define NCHALL  (NK / 64)          // 1024 total chunks
#define CK      64
#define SKW     72                 // smem row pitch (fp16); 144B rows
#define ABYTES  (CK * SKW * 2)     // 9216 = one chunk buffer
#define NGROUPS (CK * 9)           // 576 16B-groups per chunk

// static device scratch (no cudaMalloc)
__device__ __align__(16) __half g_xh[(size_t)NK * DP];        // fp16(x), 9.4 MB
__device__ __align__(16) __half g_qp[(size_t)2 * NQT * DP];   // q'h, q'l
__device__ float  g_part[(size_t)SPLITS * NQT * D66];         // 38.9 MB
__device__ float2 g_ml[SPLITS * NQT];

// ---------------- asm helpers ----------------
#define MMA16(dv, av, b0_, b1_)                                             \
    asm volatile("mma.sync.aligned.m16n8k16.row.col.f32.f16.f16.f32 "       \
                 "{%0,%1,%2,%3},{%4,%5,%6,%7},{%8,%9},{%0,%1,%2,%3};"       \
                 : "+f"(dv[0]), "+f"(dv[1]), "+f"(dv[2]), "+f"(dv[3])       \
                 : "r"(av[0]), "r"(av[1]), "r"(av[2]), "r"(av[3]),          \
                   "r"(b0_), "r"(b1_))

#define MMA8(dv, a0_, a1_, b0_)                                             \
    asm volatile("mma.sync.aligned.m16n8k8.row.col.f32.f16.f16.f32 "        \
                 "{%0,%1,%2,%3},{%4,%5},{%6},{%0,%1,%2,%3};"                \
                 : "+f"(dv[0]), "+f"(dv[1]), "+f"(dv[2]), "+f"(dv[3])       \
                 : "r"(a0_), "r"(a1_), "r"(b0_))

#define LDSM4(r0, r1, r2, r3, ad)                                           \
    asm volatile("ldmatrix.sync.aligned.m8n8.x4.shared.b16 {%0,%1,%2,%3},[%4];" \
                 : "=r"(r0), "=r"(r1), "=r"(r2), "=r"(r3) : "r"(ad))

#define LDSM2(r0, r1, ad)                                                   \
    asm volatile("ldmatrix.sync.aligned.m8n8.x2.shared.b16 {%0,%1},[%2];"   \
                 : "=r"(r0), "=r"(r1) : "r"(ad))

#define LDSM4T(r0, r1, r2, r3, ad)                                          \
    asm volatile("ldmatrix.sync.aligned.m8n8.x4.trans.shared.b16 {%0,%1,%2,%3},[%4];" \
                 : "=r"(r0), "=r"(r1), "=r"(r2), "=r"(r3) : "r"(ad))

#define LDSM2T(r0, r1, ad)                                                  \
    asm volatile("ldmatrix.sync.aligned.m8n8.x2.trans.shared.b16 {%0,%1},[%2];" \
                 : "=r"(r0), "=r"(r1) : "r"(ad))

__device__ __forceinline__ void cp16(uint32_t dst, const void* src) {
    asm volatile("cp.async.cg.shared.global [%0],[%1],16;" :: "r"(dst), "l"(src));
}
__device__ __forceinline__ void cpcommit() { asm volatile("cp.async.commit_group;"); }
__device__ __forceinline__ void cpwait1()  { asm volatile("cp.async.wait_group 1;"); }
__device__ __forceinline__ void cpwait0()  { asm volatile("cp.async.wait_group 0;"); }

__device__ __forceinline__ void split2h(float x, float y, uint32_t& hi, uint32_t& lo) {
    __half2 h = __floats2half2_rn(x, y);
    hi = *reinterpret_cast<uint32_t*>(&h);
    float rx = x - __low2float(h);
    float ry = y - __high2float(h);
    __half2 l = __floats2half2_rn(rx, ry);
    lo = *reinterpret_cast<uint32_t*>(&l);
}
__device__ __forceinline__ uint32_t pack2h(float x, float y) {
    __half2 h = __floats2half2_rn(x, y);
    return *reinterpret_cast<uint32_t*>(&h);
}
__device__ __forceinline__ uint32_t ex2h2(uint32_t a) {
    uint32_t d;
    asm("ex2.approx.f16x2 %0, %1;" : "=r"(d) : "r"(a));
    return d;
}

#define L2E 1.44269504f

// ============================================================
// Kernel 1a: q' = Wk^T q (bias cancels in softmax), fp16 hi/lo
// ============================================================
__global__ void __launch_bounds__(128)
qprime_kernel(const float* __restrict__ query, const float* __restrict__ Wk) {
    __shared__ float sW[D66 * D66];
    const int tid = threadIdx.x;
    const int row = blockIdx.x * 128 + tid;
    for (int i = tid; i < D66 * D66; i += 128) sW[i] = Wk[i];
    __syncthreads();

    float qr[D66];
    const float2* qp = (const float2*)(query + (size_t)row * D66);
    #pragma unroll
    for (int c = 0; c < 33; c++) { float2 v = qp[c]; qr[2*c] = v.x; qr[2*c+1] = v.y; }

    __half* Qh = g_qp;
    __half* Ql = g_qp + (size_t)NQT * DP;
    const size_t rb = (size_t)row * DP;

    #pragma unroll 1
    for (int j = 0; j < D66; j += 2) {
        float a0 = 0.0f, a1 = 0.0f;
        #pragma unroll
        for (int d = 0; d < D66; d++) {
            a0 = fmaf(qr[d], sW[d * D66 + j], a0);
            a1 = fmaf(qr[d], sW[d * D66 + j + 1], a1);
        }
        uint32_t hi, lo;
        split2h(a0, a1, hi, lo);
        *(uint32_t*)(Qh + rb + j) = hi;
        *(uint32_t*)(Ql + rb + j) = lo;
    }
    #pragma unroll
    for (int c = 33; c < DP / 2; c++) {
        *(uint32_t*)(Qh + rb + 2 * c) = 0u;
        *(uint32_t*)(Ql + rb + 2 * c) = 0u;
    }
}

// ============================================================
// Kernel 1b: x -> fp16, padded to DP=72
// ============================================================
__global__ void __launch_bounds__(256)
xsplit_kernel(const float* __restrict__ x) {
    const int n = blockIdx.x * 256 + threadIdx.x;
    const size_t rb = (size_t)n * DP;
    const float2* xp = (const float2*)(x + (size_t)n * D66);
    #pragma unroll
    for (int c = 0; c < 33; c++) {
        float2 v = xp[c];
        *(uint32_t*)(g_xh + rb + 2 * c) = pack2h(v.x, v.y);
    }
    #pragma unroll
    for (int c = 33; c < DP / 2; c++)
        *(uint32_t*)(g_xh + rb + 2 * c) = 0u;
}

// ============================================================
// Kernel 2: flash attention selector — 4 warps x 32 q-rows
// QK 2-pass (q'h + q'l vs fp16 X), PV 1-pass, online max.
// ============================================================
extern __shared__ __half smbuf[];

__global__ void __launch_bounds__(128)
flash_kernel() {
    const int tid  = threadIdx.x;
    const int lane = tid & 31;
    const int w    = tid >> 5;
    const int qtile = blockIdx.x % 64;
    const int split = blockIdx.x / 64;          // 0..17
    const int q0w = qtile * 128 + w * 32;
    const int chLo = (split * NCHALL) / SPLITS;
    const int chHi = ((split + 1) * NCHALL) / SPLITS;

    const int g  = lane >> 2;
    const int t  = lane & 3;
    const int q8 = lane >> 3;
    const int r  = lane & 7;

    const uint32_t sbase = (uint32_t)__cvta_generic_to_shared(smbuf);

    // ---- q' fragments (resident, hi/lo) ----
    uint32_t aqh[2][4][4], aql[2][4][4], aq8h[2][2], aq8l[2][2];
    {
        const __half* Qh = g_qp;
        const __half* Ql = g_qp + (size_t)NQT * DP;
        #pragma unroll
        for (int mt = 0; mt < 2; mt++) {
            const size_t r0 = (size_t)(q0w + 16 * mt + g) * DP;
            const size_t r1 = (size_t)(q0w + 16 * mt + g + 8) * DP;
            #pragma unroll
            for (int kc = 0; kc < 4; kc++) {
                int c0 = 16 * kc + 2 * t;
                aqh[mt][kc][0] = *(const uint32_t*)(Qh + r0 + c0);
                aqh[mt][kc][1] = *(const uint32_t*)(Qh + r1 + c0);
                aqh[mt][kc][2] = *(const uint32_t*)(Qh + r0 + c0 + 8);
                aqh[mt][kc][3] = *(const uint32_t*)(Qh + r1 + c0 + 8);
                aql[mt][kc][0] = *(const uint32_t*)(Ql + r0 + c0);
                aql[mt][kc][1] = *(const uint32_t*)(Ql + r1 + c0);
                aql[mt][kc][2] = *(const uint32_t*)(Ql + r0 + c0 + 8);
                aql[mt][kc][3] = *(const uint32_t*)(Ql + r1 + c0 + 8);
            }
            int c8 = 64 + 2 * t;
            aq8h[mt][0] = *(const uint32_t*)(Qh + r0 + c8);
            aq8h[mt][1] = *(const uint32_t*)(Qh + r1 + c8);
            aq8l[mt][0] = *(const uint32_t*)(Ql + r0 + c8);
            aq8l[mt][1] = *(const uint32_t*)(Ql + r1 + c8);
        }
    }

    const uint32_t qk_off  = ((8 * (q8 >> 1) + r) * SKW + 8 * (q8 & 1)) * 2;
    const uint32_t qk8_off = ((8 * (q8 & 1) + r) * SKW + 64) * 2;
    const uint32_t pv_off  = ((8 * (q8 & 1) + r) * SKW + 8 * (q8 >> 1)) * 2;
    const uint32_t pv2_off = ((8 * (q8 & 1) + r) * SKW + 64) * 2;

    float o[2][9][4];
    #pragma unroll
    for (int mt = 0; mt < 2; mt++)
        #pragma unroll
        for (int i = 0; i < 9; i++)
            #pragma unroll
            for (int c = 0; c < 4; c++) o[mt][i][c] = 0.0f;
    float m[4] = {-1e30f, -1e30f, -1e30f, -1e30f};
    float l[4] = {0.0f, 0.0f, 0.0f, 0.0f};

    #define PREFETCH(CH)                                                          \
    do {                                                                          \
        const size_t kb = (size_t)(CH) * CK;                                      \
        const uint32_t bb = sbase + ((CH) & 1) * ABYTES;                          \
        _Pragma("unroll")                                                         \
        for (int jj = 0; jj < 5; jj++) {                                          \
            int j = tid + jj * 128;                                               \
            if (j < NGROUPS) {                                                    \
                int row = j / 9;                                                  \
                int cc  = j - row * 9;                                            \
                const __half* src = g_xh + (kb + row) * DP + cc * 8;              \
                uint32_t dst = bb + (row * SKW + cc * 8) * 2;                     \
                cp16(dst, src);                                                   \
            }                                                                     \
        }                                                                         \
    } while (0)

    PREFETCH(chLo); cpcommit();

    for (int ch = chLo; ch < chHi; ch++) {
        if (ch + 1 < chHi) { PREFETCH(ch + 1); cpcommit(); cpwait1(); }
        else               { cpwait0(); }
        __syncthreads();

        const uint32_t sX = sbase + (ch & 1) * ABYTES;

        // ---- QK: S = (q'h + q'l) . X ----
        float s[2][8][4];
        #pragma unroll
        for (int mt = 0; mt < 2; mt++)
            #pragma unroll
            for (int i = 0; i < 8; i++)
                #pragma unroll
                for (int c = 0; c < 4; c++) s[mt][i][c] = 0.0f;

        #pragma unroll
        for (int kc = 0; kc < 4; kc++) {
            #pragma unroll
            for (int jn2 = 0; jn2 < 4; jn2++) {
                uint32_t off = (16 * jn2 * SKW + 16 * kc) * 2 + qk_off;
                uint32_t b0, b1, b2, b3;
                LDSM4(b0, b1, b2, b3, sX + off);
                #pragma unroll
                for (int mt = 0; mt < 2; mt++) {
                    MMA16(s[mt][2 * jn2],     aqh[mt][kc], b0, b1);
                    MMA16(s[mt][2 * jn2],     aql[mt][kc], b0, b1);
                    MMA16(s[mt][2 * jn2 + 1], aqh[mt][kc], b2, b3);
                    MMA16(s[mt][2 * jn2 + 1], aql[mt][kc], b2, b3);
                }
            }
        }
        #pragma unroll
        for (int jn2 = 0; jn2 < 4; jn2++) {
            uint32_t off = (16 * jn2 * SKW) * 2 + qk8_off;
            uint32_t b0, b1;
            LDSM2(b0, b1, sX + off);
            #pragma unroll
            for (int mt = 0; mt < 2; mt++) {
                MMA8(s[mt][2 * jn2],     aq8h[mt][0], aq8h[mt][1], b0);
                MMA8(s[mt][2 * jn2],     aq8l[mt][0], aq8l[mt][1], b0);
                MMA8(s[mt][2 * jn2 + 1], aq8h[mt][0], aq8h[mt][1], b1);
                MMA8(s[mt][2 * jn2 + 1], aq8l[mt][0], aq8l[mt][1], b1);
            }
        }

        // ---- online softmax: f16x2 exp2, alpha-skip, half2 l-accum ----
        uint32_t ph[2][4][4];
        #pragma unroll
        for (int mt = 0; mt < 2; mt++) {
            float mx0 = -1e30f, mx1 = -1e30f;
            #pragma unroll
            for (int i = 0; i < 8; i++) {
                mx0 = fmaxf(mx0, fmaxf(s[mt][i][0], s[mt][i][1]));
                mx1 = fmaxf(mx1, fmaxf(s[mt][i][2], s[mt][i][3]));
            }
            mx0 = fmaxf(mx0, __shfl_xor_sync(0xffffffffu, mx0, 1));
            mx0 = fmaxf(mx0, __shfl_xor_sync(0xffffffffu, mx0, 2));
            mx1 = fmaxf(mx1, __shfl_xor_sync(0xffffffffu, mx1, 1));
            mx1 = fmaxf(mx1, __shfl_xor_sync(0xffffffffu, mx1, 2));

            float mN0 = fmaxf(m[2 * mt], mx0);
            float mN1 = fmaxf(m[2 * mt + 1], mx1);
            bool nochg = (mN0 == m[2 * mt]) && (mN1 == m[2 * mt + 1]);
            if (!__all_sync(0xffffffffu, nochg)) {
                float a0 = __expf(m[2 * mt] - mN0);
                float a1 = __expf(m[2 * mt + 1] - mN1);
                l[2 * mt] *= a0; l[2 * mt + 1] *= a1;
                #pragma unroll
                for (int i = 0; i < 9; i++) {
                    o[mt][i][0] *= a0; o[mt][i][1] *= a0;
                    o[mt][i][2] *= a1; o[mt][i][3] *= a1;
                }
                m[2 * mt] = mN0; m[2 * mt + 1] = mN1;
            }
            const float mL0 = mN0 * L2E;
            const float mL1 = mN1 * L2E;

            __half2 lA2 = __floats2half2_rn(0.f, 0.f);
            __half2 lB2 = __floats2half2_rn(0.f, 0.f);
            #pragma unroll
            for (int u = 0; u < 4; u++) {
                ph[mt][u][0] = ex2h2(pack2h(fmaf(s[mt][2*u][0],   L2E, -mL0),
                                            fmaf(s[mt][2*u][1],   L2E, -mL0)));
                ph[mt][u][1] = ex2h2(pack2h(fmaf(s[mt][2*u][2],   L2E, -mL1),
                                            fmaf(s[mt][2*u][3],   L2E, -mL1)));
                ph[mt][u][2] = ex2h2(pack2h(fmaf(s[mt][2*u+1][0], L2E, -mL0),
                                            fmaf(s[mt][2*u+1][1], L2E, -mL0)));
                ph[mt][u][3] = ex2h2(pack2h(fmaf(s[mt][2*u+1][2], L2E, -mL1),
                                            fmaf(s[mt][2*u+1][3], L2E, -mL1)));
                lA2 = __hadd2(lA2, *reinterpret_cast<__half2*>(&ph[mt][u][0]));
                lA2 = __hadd2(lA2, *reinterpret_cast<__half2*>(&ph[mt][u][2]));
                lB2 = __hadd2(lB2, *reinterpret_cast<__half2*>(&ph[mt][u][1]));
                lB2 = __hadd2(lB2, *reinterpret_cast<__half2*>(&ph[mt][u][3]));
            }
            float2 va = __half22float2(lA2);
            float2 vb = __half22float2(lB2);
            l[2 * mt]     += va.x + va.y;
            l[2 * mt + 1] += vb.x + vb.y;
        }

        // ---- PV: O += P . X ----
        #pragma unroll
        for (int kc2 = 0; kc2 < 4; kc2++) {
            #pragma unroll
            for (int dn2 = 0; dn2 < 4; dn2++) {
                uint32_t off = (16 * kc2 * SKW + 16 * dn2) * 2 + pv_off;
                uint32_t b0, b1, b2, b3;
                LDSM4T(b0, b1, b2, b3, sX + off);
                #pragma unroll
                for (int mt = 0; mt < 2; mt++) {
                    MMA16(o[mt][2 * dn2],     ph[mt][kc2], b0, b1);
                    MMA16(o[mt][2 * dn2 + 1], ph[mt][kc2], b2, b3);
                }
            }
            {
                uint32_t off = (16 * kc2 * SKW) * 2 + pv2_off;
                uint32_t b0, b1;
                LDSM2T(b0, b1, sX + off);
                #pragma unroll
                for (int mt = 0; mt < 2; mt++)
                    MMA16(o[mt][8], ph[mt][kc2], b0, b1);
            }
        }
        __syncthreads();
    }

    // ---- epilogue ----
    #pragma unroll
    for (int i = 0; i < 4; i++) {
        l[i] += __shfl_xor_sync(0xffffffffu, l[i], 1);
        l[i] += __shfl_xor_sync(0xffffffffu, l[i], 2);
    }
    if ((lane & 3) == 0) {
        #pragma unroll
        for (int mt = 0; mt < 2; mt++) {
            g_ml[split * NQT + q0w + 16 * mt + g]     = make_float2(m[2*mt],   l[2*mt]);
            g_ml[split * NQT + q0w + 16 * mt + g + 8] = make_float2(m[2*mt+1], l[2*mt+1]);
        }
    }
    const size_t ob = (size_t)split * NQT;
    #pragma unroll
    for (int mt = 0; mt < 2; mt++) {
        #pragma unroll
        for (int dn = 0; dn < 9; dn++) {
            int d0 = 8 * dn + 2 * t;
            if (d0 < D66) {
                *(float2*)(g_part + (ob + q0w + 16*mt + g)     * D66 + d0) =
                    make_float2(o[mt][dn][0], o[mt][dn][1]);
                *(float2*)(g_part + (ob + q0w + 16*mt + g + 8) * D66 + d0) =
                    make_float2(o[mt][dn][2], o[mt][dn][3]);
            }
        }
    }
}

// ============================================================
// Kernel 3: combine — 4 threads per query, LSE merge over 18
// ============================================================
__global__ void __launch_bounds__(256)
combine_kernel(float* __restrict__ out) {
    const int tid = threadIdx.x;
    const int part = tid & 3;
    const int q = blockIdx.x * 64 + (tid >> 2);

    float M = -1e30f;
    float mx[SPLITS], lx[SPLITS];
    #pragma unroll
    for (int s = 0; s < SPLITS; s++) {
        float2 v = g_ml[s * NQT + q];
        mx[s] = v.x; lx[s] = v.y;
        M = fmaxf(M, v.x);
    }
    float wgt[SPLITS];
    float l = 0.0f;
    #pragma unroll
    for (int s = 0; s < SPLITS; s++) {
        wgt[s] = __expf(mx[s] - M);
        l += wgt[s] * lx[s];
    }
    float inv = 1.0f / l;

    #pragma unroll
    for (int i = 0; i < 9; i++) {
        int pr = part * 9 + i;
        if (pr < 33) {
            float ax = 0.0f, ay = 0.0f;
            #pragma unroll
            for (int s = 0; s < SPLITS; s++) {
                float2 v = *(const float2*)(g_part + ((size_t)s * NQT + q) * D66 + 2 * pr);
                ax = fmaf(wgt[s], v.x, ax);
                ay = fmaf(wgt[s], v.y, ay);
            }
            out[(size_t)q * D66 + 2 * pr]     = ax * inv;
            out[(size_t)q * D66 + 2 * pr + 1] = ay * inv;
        }
    }
}

// ============================================================
extern "C" void kernel_launch(void* const* d_in, const int* in_sizes, int n_in,
                              void* d_out, int out_size) {
    const float* x     = (const float*)d_in[0];
    const float* query = (const float*)d_in[1];
    const float* Wk    = (const float*)d_in[2];
    // bk unused: q.b cancels in softmax
    float* out = (float*)d_out;

    const int smem_bytes = 2 * ABYTES;   // 18432
    cudaFuncSetAttribute(flash_kernel,
                         cudaFuncAttributeMaxDynamicSharedMemorySize, smem_bytes);

    qprime_kernel<<<NQT / 128, 128>>>(query, Wk);
    xsplit_kernel<<<NK / 256, 256>>>(x);
    flash_kernel<<<64 * SPLITS, 128, smem_bytes>>>();
    combine_kernel<<<NQT / 64, 256>>>(out);
}

// round 9
// speedup vs baseline: 18.6296x; 1.0277x over previous
#include <cuda_runtime.h>
#include <cuda_fp16.h>
#include <cstdint>

#define D66     66
#define DP      72                 // padded dim (4x k16 + 1x k8)
#define NK      65536
#define NQT     8192
#define SPLITS  18
#define NCHALL  (NK / 64)          // 1024 total chunks
#define CK      64
#define SKW     72                 // smem row pitch (fp16); 144B rows
#define ABYTES  (CK * SKW * 2)     // 9216 = one chunk buffer
#define NBUF    4
#define NGROUPS (CK * 9)           // 576 16B-groups per chunk

// static device scratch (no cudaMalloc)
__device__ __align__(16) __half g_xh[(size_t)NK * DP];        // fp16(x)
__device__ __align__(16) __half g_qp[(size_t)2 * NQT * DP];   // q'h, q'l
__device__ float  g_part[(size_t)SPLITS * NQT * D66];
__device__ float2 g_ml[SPLITS * NQT];

// ---------------- asm helpers ----------------
#define MMA16(dv, av, b0_, b1_)                                             \
    asm volatile("mma.sync.aligned.m16n8k16.row.col.f32.f16.f16.f32 "       \
                 "{%0,%1,%2,%3},{%4,%5,%6,%7},{%8,%9},{%0,%1,%2,%3};"       \
                 : "+f"(dv[0]), "+f"(dv[1]), "+f"(dv[2]), "+f"(dv[3])       \
                 : "r"(av[0]), "r"(av[1]), "r"(av[2]), "r"(av[3]),          \
                   "r"(b0_), "r"(b1_))

#define MMA8(dv, a0_, a1_, b0_)                                             \
    asm volatile("mma.sync.aligned.m16n8k8.row.col.f32.f16.f16.f32 "        \
                 "{%0,%1,%2,%3},{%4,%5},{%6},{%0,%1,%2,%3};"                \
                 : "+f"(dv[0]), "+f"(dv[1]), "+f"(dv[2]), "+f"(dv[3])       \
                 : "r"(a0_), "r"(a1_), "r"(b0_))

#define LDSM4(r0, r1, r2, r3, ad)                                           \
    asm volatile("ldmatrix.sync.aligned.m8n8.x4.shared.b16 {%0,%1,%2,%3},[%4];" \
                 : "=r"(r0), "=r"(r1), "=r"(r2), "=r"(r3) : "r"(ad))

#define LDSM2(r0, r1, ad)                                                   \
    asm volatile("ldmatrix.sync.aligned.m8n8.x2.shared.b16 {%0,%1},[%2];"   \
                 : "=r"(r0), "=r"(r1) : "r"(ad))

#define LDSM4T(r0, r1, r2, r3, ad)                                          \
    asm volatile("ldmatrix.sync.aligned.m8n8.x4.trans.shared.b16 {%0,%1,%2,%3},[%4];" \
                 : "=r"(r0), "=r"(r1), "=r"(r2), "=r"(r3) : "r"(ad))

#define LDSM2T(r0, r1, ad)                                                  \
    asm volatile("ldmatrix.sync.aligned.m8n8.x2.trans.shared.b16 {%0,%1},[%2];" \
                 : "=r"(r0), "=r"(r1) : "r"(ad))

__device__ __forceinline__ void cp16(uint32_t dst, const void* src) {
    asm volatile("cp.async.cg.shared.global [%0],[%1],16;" :: "r"(dst), "l"(src));
}
__device__ __forceinline__ void cpcommit() { asm volatile("cp.async.commit_group;"); }
__device__ __forceinline__ void cpwait2()  { asm volatile("cp.async.wait_group 2;"); }

__device__ __forceinline__ void split2h(float x, float y, uint32_t& hi, uint32_t& lo) {
    __half2 h = __floats2half2_rn(x, y);
    hi = *reinterpret_cast<uint32_t*>(&h);
    float rx = x - __low2float(h);
    float ry = y - __high2float(h);
    __half2 l = __floats2half2_rn(rx, ry);
    lo = *reinterpret_cast<uint32_t*>(&l);
}
__device__ __forceinline__ uint32_t pack2h(float x, float y) {
    __half2 h = __floats2half2_rn(x, y);
    return *reinterpret_cast<uint32_t*>(&h);
}
__device__ __forceinline__ uint32_t ex2h2(uint32_t a) {
    uint32_t d;
    asm("ex2.approx.f16x2 %0, %1;" : "=r"(d) : "r"(a));
    return d;
}

#define L2E 1.44269504f

// ============================================================
// Kernel 1a: q' = Wk^T q (bias cancels in softmax), fp16 hi/lo
// ============================================================
__global__ void __launch_bounds__(128)
qprime_kernel(const float* __restrict__ query, const float* __restrict__ Wk) {
    __shared__ float sW[D66 * D66];
    const int tid = threadIdx.x;
    const int row = blockIdx.x * 128 + tid;
    for (int i = tid; i < D66 * D66; i += 128) sW[i] = Wk[i];
    __syncthreads();

    float qr[D66];
    const float2* qp = (const float2*)(query + (size_t)row * D66);
    #pragma unroll
    for (int c = 0; c < 33; c++) { float2 v = qp[c]; qr[2*c] = v.x; qr[2*c+1] = v.y; }

    __half* Qh = g_qp;
    __half* Ql = g_qp + (size_t)NQT * DP;
    const size_t rb = (size_t)row * DP;

    #pragma unroll 1
    for (int j = 0; j < D66; j += 2) {
        float a0 = 0.0f, a1 = 0.0f;
        #pragma unroll
        for (int d = 0; d < D66; d++) {
            a0 = fmaf(qr[d], sW[d * D66 + j], a0);
            a1 = fmaf(qr[d], sW[d * D66 + j + 1], a1);
        }
        uint32_t hi, lo;
        split2h(a0, a1, hi, lo);
        *(uint32_t*)(Qh + rb + j) = hi;
        *(uint32_t*)(Ql + rb + j) = lo;
    }
    #pragma unroll
    for (int c = 33; c < DP / 2; c++) {
        *(uint32_t*)(Qh + rb + 2 * c) = 0u;
        *(uint32_t*)(Ql + rb + 2 * c) = 0u;
    }
}

// ============================================================
// Kernel 1b: x -> fp16, padded to DP=72
// ============================================================
__global__ void __launch_bounds__(256)
xsplit_kernel(const float* __restrict__ x) {
    const int n = blockIdx.x * 256 + threadIdx.x;
    const size_t rb = (size_t)n * DP;
    const float2* xp = (const float2*)(x + (size_t)n * D66);
    #pragma unroll
    for (int c = 0; c < 33; c++) {
        float2 v = xp[c];
        *(uint32_t*)(g_xh + rb + 2 * c) = pack2h(v.x, v.y);
    }
    #pragma unroll
    for (int c = 33; c < DP / 2; c++)
        *(uint32_t*)(g_xh + rb + 2 * c) = 0u;
}

// ============================================================
// Kernel 2: flash attention selector — 4 warps x 32 q-rows
// QK 2-pass, PV 1-pass, online max, 4-buffer ring, 1 sync/chunk
// ============================================================
extern __shared__ __half smbuf[];

__global__ void __launch_bounds__(128, 2)
flash_kernel() {
    const int tid  = threadIdx.x;
    const int lane = tid & 31;
    const int w    = tid >> 5;
    const int qtile = blockIdx.x % 64;
    const int split = blockIdx.x / 64;          // 0..17
    const int q0w = qtile * 128 + w * 32;
    const int chLo = (split * NCHALL) / SPLITS;
    const int chHi = ((split + 1) * NCHALL) / SPLITS;

    const int g  = lane >> 2;
    const int t  = lane & 3;
    const int q8 = lane >> 3;
    const int r  = lane & 7;

    const uint32_t sbase = (uint32_t)__cvta_generic_to_shared(smbuf);

    // ---- q' fragments (resident, hi/lo) ----
    uint32_t aqh[2][4][4], aql[2][4][4], aq8h[2][2], aq8l[2][2];
    {
        const __half* Qh = g_qp;
        const __half* Ql = g_qp + (size_t)NQT * DP;
        #pragma unroll
        for (int mt = 0; mt < 2; mt++) {
            const size_t r0 = (size_t)(q0w + 16 * mt + g) * DP;
            const size_t r1 = (size_t)(q0w + 16 * mt + g + 8) * DP;
            #pragma unroll
            for (int kc = 0; kc < 4; kc++) {
                int c0 = 16 * kc + 2 * t;
                aqh[mt][kc][0] = *(const uint32_t*)(Qh + r0 + c0);
                aqh[mt][kc][1] = *(const uint32_t*)(Qh + r1 + c0);
                aqh[mt][kc][2] = *(const uint32_t*)(Qh + r0 + c0 + 8);
                aqh[mt][kc][3] = *(const uint32_t*)(Qh + r1 + c0 + 8);
                aql[mt][kc][0] = *(const uint32_t*)(Ql + r0 + c0);
                aql[mt][kc][1] = *(const uint32_t*)(Ql + r1 + c0);
                aql[mt][kc][2] = *(const uint32_t*)(Ql + r0 + c0 + 8);
                aql[mt][kc][3] = *(const uint32_t*)(Ql + r1 + c0 + 8);
            }
            int c8 = 64 + 2 * t;
            aq8h[mt][0] = *(const uint32_t*)(Qh + r0 + c8);
            aq8h[mt][1] = *(const uint32_t*)(Qh + r1 + c8);
            aq8l[mt][0] = *(const uint32_t*)(Ql + r0 + c8);
            aq8l[mt][1] = *(const uint32_t*)(Ql + r1 + c8);
        }
    }

    const uint32_t qk_off  = ((8 * (q8 >> 1) + r) * SKW + 8 * (q8 & 1)) * 2;
    const uint32_t qk8_off = ((8 * (q8 & 1) + r) * SKW + 64) * 2;
    const uint32_t pv_off  = ((8 * (q8 & 1) + r) * SKW + 8 * (q8 >> 1)) * 2;
    const uint32_t pv2_off = ((8 * (q8 & 1) + r) * SKW + 64) * 2;

    float o[2][9][4];
    #pragma unroll
    for (int mt = 0; mt < 2; mt++)
        #pragma unroll
        for (int i = 0; i < 9; i++)
            #pragma unroll
            for (int c = 0; c < 4; c++) o[mt][i][c] = 0.0f;
    float m[4] = {-1e30f, -1e30f, -1e30f, -1e30f};
    float l[4] = {0.0f, 0.0f, 0.0f, 0.0f};

    #define PREFETCH(CH)                                                          \
    do {                                                                          \
        const size_t kb = (size_t)(CH) * CK;                                      \
        const uint32_t bb = sbase + ((CH) & (NBUF - 1)) * ABYTES;                 \
        _Pragma("unroll")                                                         \
        for (int jj = 0; jj < 5; jj++) {                                          \
            int j = tid + jj * 128;                                               \
            if (j < NGROUPS) {                                                    \
                int row = j / 9;                                                  \
                int cc  = j - row * 9;                                            \
                const __half* src = g_xh + (kb + row) * DP + cc * 8;              \
                uint32_t dst = bb + (row * SKW + cc * 8) * 2;                     \
                cp16(dst, src);                                                   \
            }                                                                     \
        }                                                                         \
    } while (0)

    // prime the ring: chunks chLo, chLo+1 in flight
    PREFETCH(chLo); cpcommit();
    if (chLo + 1 < chHi) PREFETCH(chLo + 1);
    cpcommit();

    for (int ch = chLo; ch < chHi; ch++) {
        // issue ch+2 (possibly empty group — keeps wait_group count constant)
        if (ch + 2 < chHi) PREFETCH(ch + 2);
        cpcommit();
        cpwait2();            // chunk ch's group complete (<=2 newer pending)
        __syncthreads();      // single barrier per chunk

        const uint32_t sX = sbase + (ch & (NBUF - 1)) * ABYTES;

        // ---- QK: S = (q'h + q'l) . X ----
        float s[2][8][4];
        #pragma unroll
        for (int mt = 0; mt < 2; mt++)
            #pragma unroll
            for (int i = 0; i < 8; i++)
                #pragma unroll
                for (int c = 0; c < 4; c++) s[mt][i][c] = 0.0f;

        #pragma unroll
        for (int kc = 0; kc < 4; kc++) {
            #pragma unroll
            for (int jn2 = 0; jn2 < 4; jn2++) {
                uint32_t off = (16 * jn2 * SKW + 16 * kc) * 2 + qk_off;
                uint32_t b0, b1, b2, b3;
                LDSM4(b0, b1, b2, b3, sX + off);
                #pragma unroll
                for (int mt = 0; mt < 2; mt++) {
                    MMA16(s[mt][2 * jn2],     aqh[mt][kc], b0, b1);
                    MMA16(s[mt][2 * jn2],     aql[mt][kc], b0, b1);
                    MMA16(s[mt][2 * jn2 + 1], aqh[mt][kc], b2, b3);
                    MMA16(s[mt][2 * jn2 + 1], aql[mt][kc], b2, b3);
                }
            }
        }
        #pragma unroll
        for (int jn2 = 0; jn2 < 4; jn2++) {
            uint32_t off = (16 * jn2 * SKW) * 2 + qk8_off;
            uint32_t b0, b1;
            LDSM2(b0, b1, sX + off);
            #pragma unroll
            for (int mt = 0; mt < 2; mt++) {
                MMA8(s[mt][2 * jn2],     aq8h[mt][0], aq8h[mt][1], b0);
                MMA8(s[mt][2 * jn2],     aq8l[mt][0], aq8l[mt][1], b0);
                MMA8(s[mt][2 * jn2 + 1], aq8h[mt][0], aq8h[mt][1], b1);
                MMA8(s[mt][2 * jn2 + 1], aq8l[mt][0], aq8l[mt][1], b1);
            }
        }

        // ---- online softmax: f16x2 exp2, alpha-skip, half2 l-accum ----
        uint32_t ph[2][4][4];
        #pragma unroll
        for (int mt = 0; mt < 2; mt++) {
            float mx0 = -1e30f, mx1 = -1e30f;
            #pragma unroll
            for (int i = 0; i < 8; i++) {
                mx0 = fmaxf(mx0, fmaxf(s[mt][i][0], s[mt][i][1]));
                mx1 = fmaxf(mx1, fmaxf(s[mt][i][2], s[mt][i][3]));
            }
            mx0 = fmaxf(mx0, __shfl_xor_sync(0xffffffffu, mx0, 1));
            mx0 = fmaxf(mx0, __shfl_xor_sync(0xffffffffu, mx0, 2));
            mx1 = fmaxf(mx1, __shfl_xor_sync(0xffffffffu, mx1, 1));
            mx1 = fmaxf(mx1, __shfl_xor_sync(0xffffffffu, mx1, 2));

            float mN0 = fmaxf(m[2 * mt], mx0);
            float mN1 = fmaxf(m[2 * mt + 1], mx1);
            bool nochg = (mN0 == m[2 * mt]) && (mN1 == m[2 * mt + 1]);
            if (!__all_sync(0xffffffffu, nochg)) {
                float a0 = __expf(m[2 * mt] - mN0);
                float a1 = __expf(m[2 * mt + 1] - mN1);
                l[2 * mt] *= a0; l[2 * mt + 1] *= a1;
                #pragma unroll
                for (int i = 0; i < 9; i++) {
                    o[mt][i][0] *= a0; o[mt][i][1] *= a0;
                    o[mt][i][2] *= a1; o[mt][i][3] *= a1;
                }
                m[2 * mt] = mN0; m[2 * mt + 1] = mN1;
            }
            const float mL0 = mN0 * L2E;
            const float mL1 = mN1 * L2E;

            __half2 lA2 = __floats2half2_rn(0.f, 0.f);
            __half2 lB2 = __floats2half2_rn(0.f, 0.f);
            #pragma unroll
            for (int u = 0; u < 4; u++) {
                ph[mt][u][0] = ex2h2(pack2h(fmaf(s[mt][2*u][0],   L2E, -mL0),
                                            fmaf(s[mt][2*u][1],   L2E, -mL0)));
                ph[mt][u][1] = ex2h2(pack2h(fmaf(s[mt][2*u][2],   L2E, -mL1),
                                            fmaf(s[mt][2*u][3],   L2E, -mL1)));
                ph[mt][u][2] = ex2h2(pack2h(fmaf(s[mt][2*u+1][0], L2E, -mL0),
                                            fmaf(s[mt][2*u+1][1], L2E, -mL0)));
                ph[mt][u][3] = ex2h2(pack2h(fmaf(s[mt][2*u+1][2], L2E, -mL1),
                                            fmaf(s[mt][2*u+1][3], L2E, -mL1)));
                lA2 = __hadd2(lA2, *reinterpret_cast<__half2*>(&ph[mt][u][0]));
                lA2 = __hadd2(lA2, *reinterpret_cast<__half2*>(&ph[mt][u][2]));
                lB2 = __hadd2(lB2, *reinterpret_cast<__half2*>(&ph[mt][u][1]));
                lB2 = __hadd2(lB2, *reinterpret_cast<__half2*>(&ph[mt][u][3]));
            }
            float2 va = __half22float2(lA2);
            float2 vb = __half22float2(lB2);
            l[2 * mt]     += va.x + va.y;
            l[2 * mt + 1] += vb.x + vb.y;
        }

        // ---- PV: O += P . X ----
        #pragma unroll
        for (int kc2 = 0; kc2 < 4; kc2++) {
            #pragma unroll
            for (int dn2 = 0; dn2 < 4; dn2++) {
                uint32_t off = (16 * kc2 * SKW + 16 * dn2) * 2 + pv_off;
                uint32_t b0, b1, b2, b3;
                LDSM4T(b0, b1, b2, b3, sX + off);
                #pragma unroll
                for (int mt = 0; mt < 2; mt++) {
                    MMA16(o[mt][2 * dn2],     ph[mt][kc2], b0, b1);
                    MMA16(o[mt][2 * dn2 + 1], ph[mt][kc2], b2, b3);
                }
            }
            {
                uint32_t off = (16 * kc2 * SKW) * 2 + pv2_off;
                uint32_t b0, b1;
                LDSM2T(b0, b1, sX + off);
                #pragma unroll
                for (int mt = 0; mt < 2; mt++)
                    MMA16(o[mt][8], ph[mt][kc2], b0, b1);
            }
        }
        // no trailing sync: ring-of-4 guarantees prefetch(ch+2) can't
        // touch any buffer still being read (proof: all warps passed the
        // iter-(ch-1) barrier, so none is before compute(ch-1)).
    }

    // ---- epilogue ----
    #pragma unroll
    for (int i = 0; i < 4; i++) {
        l[i] += __shfl_xor_sync(0xffffffffu, l[i], 1);
        l[i] += __shfl_xor_sync(0xffffffffu, l[i], 2);
    }
    if ((lane & 3) == 0) {
        #pragma unroll
        for (int mt = 0; mt < 2; mt++) {
            g_ml[split * NQT + q0w + 16 * mt + g]     = make_float2(m[2*mt],   l[2*mt]);
            g_ml[split * NQT + q0w + 16 * mt + g + 8] = make_float2(m[2*mt+1], l[2*mt+1]);
        }
    }
    const size_t ob = (size_t)split * NQT;
    #pragma unroll
    for (int mt = 0; mt < 2; mt++) {
        #pragma unroll
        for (int dn = 0; dn < 9; dn++) {
            int d0 = 8 * dn + 2 * t;
            if (d0 < D66) {
                *(float2*)(g_part + (ob + q0w + 16*mt + g)     * D66 + d0) =
                    make_float2(o[mt][dn][0], o[mt][dn][1]);
                *(float2*)(g_part + (ob + q0w + 16*mt + g + 8) * D66 + d0) =
                    make_float2(o[mt][dn][2], o[mt][dn][3]);
            }
        }
    }
}

// ============================================================
// Kernel 3: combine — 4 threads per query, LSE merge over 18
// ============================================================
__global__ void __launch_bounds__(256)
combine_kernel(float* __restrict__ out) {
    const int tid = threadIdx.x;
    const int part = tid & 3;
    const int q = blockIdx.x * 64 + (tid >> 2);

    float M = -1e30f;
    float mx[SPLITS], lx[SPLITS];
    #pragma unroll
    for (int s = 0; s < SPLITS; s++) {
        float2 v = g_ml[s * NQT + q];
        mx[s] = v.x; lx[s] = v.y;
        M = fmaxf(M, v.x);
    }
    float wgt[SPLITS];
    float l = 0.0f;
    #pragma unroll
    for (int s = 0; s < SPLITS; s++) {
        wgt[s] = __expf(mx[s] - M);
        l += wgt[s] * lx[s];
    }
    float inv = 1.0f / l;

    #pragma unroll
    for (int i = 0; i < 9; i++) {
        int pr = part * 9 + i;
        if (pr < 33) {
            float ax = 0.0f, ay = 0.0f;
            #pragma unroll
            for (int s = 0; s < SPLITS; s++) {
                float2 v = *(const float2*)(g_part + ((size_t)s * NQT + q) * D66 + 2 * pr);
                ax = fmaf(wgt[s], v.x, ax);
                ay = fmaf(wgt[s], v.y, ay);
            }
            out[(size_t)q * D66 + 2 * pr]     = ax * inv;
            out[(size_t)q * D66 + 2 * pr + 1] = ay * inv;
        }
    }
}

// ============================================================
extern "C" void kernel_launch(void* const* d_in, const int* in_sizes, int n_in,
                              void* d_out, int out_size) {
    const float* x     = (const float*)d_in[0];
    const float* query = (const float*)d_in[1];
    const float* Wk    = (const float*)d_in[2];
    // bk unused: q.b cancels in softmax
    float* out = (float*)d_out;

    const int smem_bytes = NBUF * ABYTES;   // 36864
    cudaFuncSetAttribute(flash_kernel,
                         cudaFuncAttributeMaxDynamicSharedMemorySize, smem_bytes);

    qprime_kernel<<<NQT / 128, 128>>>(query, Wk);
    xsplit_kernel<<<NK / 256, 256>>>(x);
    flash_kernel<<<64 * SPLITS, 128, smem_bytes>>>();
    combine_kernel<<<NQT / 64, 256>>>(out);
}